// round 1
// baseline (speedup 1.0000x reference)
#include <cuda_runtime.h>
#include <math.h>

#define CCH   512
#define NTOK  4096
#define BATCH 8
#define NG    32
#define CPG   16

// -------- scratch (device globals; no allocation allowed) --------
__device__ float g_h[(size_t)BATCH * CCH * NTOK];   // group-normed activations [b,c,n]
__device__ float g_q[(size_t)BATCH * CCH * NTOK];
__device__ float g_k[(size_t)BATCH * CCH * NTOK];
__device__ float g_v[(size_t)BATCH * CCH * NTOK];
__device__ float g_s[(size_t)BATCH * NTOK * NTOK];  // attention logits / probs (in-place softmax)

// ============================================================================
// GroupNorm: one block per (batch, group). 16 channels x 4096 = 65536 floats.
// ============================================================================
__global__ __launch_bounds__(512) void gn_kernel(const float* __restrict__ x,
                                                 const float* __restrict__ sc,
                                                 const float* __restrict__ bi) {
    int bg = blockIdx.x;  // b*32 + g
    const float4* xp = (const float4*)(x + (size_t)bg * CPG * NTOK);
    float4* hp = (float4*)(g_h + (size_t)bg * CPG * NTOK);
    int tid = threadIdx.x;

    const int TOT4 = CPG * NTOK / 4;  // 16384 float4
    float s = 0.f, ss = 0.f;
    for (int i = tid; i < TOT4; i += 512) {
        float4 v = xp[i];
        s  += v.x + v.y + v.z + v.w;
        ss += v.x * v.x + v.y * v.y + v.z * v.z + v.w * v.w;
    }
    __shared__ float rs[16], rss[16];
    for (int o = 16; o; o >>= 1) {
        s  += __shfl_xor_sync(0xffffffffu, s, o);
        ss += __shfl_xor_sync(0xffffffffu, ss, o);
    }
    if ((tid & 31) == 0) { rs[tid >> 5] = s; rss[tid >> 5] = ss; }
    __syncthreads();
    __shared__ float mean_s, rstd_s;
    if (tid == 0) {
        float S = 0.f, SS = 0.f;
        for (int w = 0; w < 16; w++) { S += rs[w]; SS += rss[w]; }
        float inv_n = 1.0f / (float)(CPG * NTOK);
        float mean = S * inv_n;
        float var  = SS * inv_n - mean * mean;
        mean_s = mean;
        rstd_s = rsqrtf(var + 1e-6f);
    }
    __syncthreads();
    float mean = mean_s, rstd = rstd_s;
    int g = bg & (NG - 1);

    // per-channel affine folded: y = x*a + b2, a = rstd*scale, b2 = bias - mean*a
    __shared__ float a_s[CPG], b_s[CPG];
    if (tid < CPG) {
        float a = rstd * sc[g * CPG + tid];
        a_s[tid] = a;
        b_s[tid] = bi[g * CPG + tid] - mean * a;
    }
    __syncthreads();
    for (int i = tid; i < TOT4; i += 512) {
        int cl = i >> 10;  // i*4 >> 12
        float a = a_s[cl], b2 = b_s[cl];
        float4 v = xp[i];
        v.x = v.x * a + b2; v.y = v.y * a + b2; v.z = v.z * a + b2; v.w = v.w * a + b2;
        hp[i] = v;
    }
}

// ============================================================================
// Shared GEMM tile config: 128x128x8, 256 threads, 8x8 per thread
// ============================================================================
#define BM 128
#define BN 128
#define BK 8

#define GEMM_COMPUTE_BODY()                                              \
    _Pragma("unroll")                                                    \
    for (int k = 0; k < BK; k++) {                                       \
        float af[8], bf[8];                                              \
        *(float4*)&af[0] = *(const float4*)&As[k][ty * 8];               \
        *(float4*)&af[4] = *(const float4*)&As[k][ty * 8 + 4];           \
        *(float4*)&bf[0] = *(const float4*)&Bs[k][tx * 8];               \
        *(float4*)&bf[4] = *(const float4*)&Bs[k][tx * 8 + 4];           \
        _Pragma("unroll")                                                \
        for (int i = 0; i < 8; i++)                                      \
            _Pragma("unroll")                                            \
            for (int j = 0; j < 8; j++) acc[i][j] += af[i] * bf[j];      \
    }

// ============================================================================
// QKV projection: out[b,o,n] = bias[o] + sum_c W[o,c] * h[b,c,n]
// grid: (NTOK/BN=32, CCH/BM=4, BATCH*3=24)
// ============================================================================
__global__ __launch_bounds__(256) void qkv_kernel(
    const float* __restrict__ wq, const float* __restrict__ bq,
    const float* __restrict__ wk, const float* __restrict__ bk,
    const float* __restrict__ wv, const float* __restrict__ bv) {
    int z = blockIdx.z;
    int b = z / 3, wsel = z - 3 * b;
    const float* W    = (wsel == 0) ? wq : (wsel == 1) ? wk : wv;
    const float* bias = (wsel == 0) ? bq : (wsel == 1) ? bk : bv;
    float* outg       = (wsel == 0) ? g_q : (wsel == 1) ? g_k : g_v;

    const float* Hb = g_h + (size_t)b * CCH * NTOK;
    float* Ob = outg + (size_t)b * CCH * NTOK;
    int n0 = blockIdx.x * BN, m0 = blockIdx.y * BM;

    __shared__ float As[BK][BM];
    __shared__ float Bs[BK][BN];
    int tid = threadIdx.x;
    int tx = tid & 15, ty = tid >> 4;

    float acc[8][8];
#pragma unroll
    for (int i = 0; i < 8; i++)
#pragma unroll
        for (int j = 0; j < 8; j++) acc[i][j] = 0.f;

    int am = tid >> 1, ak = (tid & 1) * 4;         // A: W[m0+am, k0+ak..+3]
    int bk_ = tid >> 5, bn_ = (tid & 31) * 4;      // B: h[k0+bk_, n0+bn_..+3]

    for (int k0 = 0; k0 < CCH; k0 += BK) {
        float4 a4 = *(const float4*)(W + (size_t)(m0 + am) * CCH + k0 + ak);
        As[ak + 0][am] = a4.x; As[ak + 1][am] = a4.y;
        As[ak + 2][am] = a4.z; As[ak + 3][am] = a4.w;
        *(float4*)&Bs[bk_][bn_] =
            *(const float4*)(Hb + (size_t)(k0 + bk_) * NTOK + n0 + bn_);
        __syncthreads();
        GEMM_COMPUTE_BODY();
        __syncthreads();
    }

#pragma unroll
    for (int i = 0; i < 8; i++) {
        int row = m0 + ty * 8 + i;
        float bv_ = bias[row];
        float* op = Ob + (size_t)row * NTOK + n0 + tx * 8;
        float4 o0 = { acc[i][0] + bv_, acc[i][1] + bv_, acc[i][2] + bv_, acc[i][3] + bv_ };
        float4 o1 = { acc[i][4] + bv_, acc[i][5] + bv_, acc[i][6] + bv_, acc[i][7] + bv_ };
        *(float4*)op = o0;
        *(float4*)(op + 4) = o1;
    }
}

// ============================================================================
// S = scale * Q^T K : S[b,i,j] = scale * sum_c q[b,c,i] k[b,c,j]
// grid: (NTOK/BN=32, NTOK/BM=32, BATCH)
// ============================================================================
__global__ __launch_bounds__(256) void s_kernel() {
    int b = blockIdx.z;
    const float* Qb = g_q + (size_t)b * CCH * NTOK;
    const float* Kb = g_k + (size_t)b * CCH * NTOK;
    float* Sb = g_s + (size_t)b * NTOK * NTOK;
    int n0 = blockIdx.x * BN, m0 = blockIdx.y * BM;

    __shared__ float As[BK][BM];
    __shared__ float Bs[BK][BN];
    int tid = threadIdx.x;
    int tx = tid & 15, ty = tid >> 4;

    float acc[8][8];
#pragma unroll
    for (int i = 0; i < 8; i++)
#pragma unroll
        for (int j = 0; j < 8; j++) acc[i][j] = 0.f;

    int lk = tid >> 5, lm = (tid & 31) * 4;

    for (int k0 = 0; k0 < CCH; k0 += BK) {
        *(float4*)&As[lk][lm] = *(const float4*)(Qb + (size_t)(k0 + lk) * NTOK + m0 + lm);
        *(float4*)&Bs[lk][lm] = *(const float4*)(Kb + (size_t)(k0 + lk) * NTOK + n0 + lm);
        __syncthreads();
        GEMM_COMPUTE_BODY();
        __syncthreads();
    }

    const float scale = 0.044194173824159216f;  // 512^-0.5
#pragma unroll
    for (int i = 0; i < 8; i++) {
        float* op = Sb + (size_t)(m0 + ty * 8 + i) * NTOK + n0 + tx * 8;
        float4 o0 = { acc[i][0] * scale, acc[i][1] * scale, acc[i][2] * scale, acc[i][3] * scale };
        float4 o1 = { acc[i][4] * scale, acc[i][5] * scale, acc[i][6] * scale, acc[i][7] * scale };
        *(float4*)op = o0;
        *(float4*)(op + 4) = o1;
    }
}

// ============================================================================
// Row softmax over g_s, in place. One block per row (BATCH*NTOK rows).
// ============================================================================
__global__ __launch_bounds__(256) void softmax_kernel() {
    size_t row = blockIdx.x;
    float4* p = (float4*)(g_s + row * NTOK);
    int tid = threadIdx.x;

    float4 v[4];
    float m = -1e30f;
#pragma unroll
    for (int i = 0; i < 4; i++) {
        v[i] = p[tid + 256 * i];
        m = fmaxf(m, fmaxf(fmaxf(v[i].x, v[i].y), fmaxf(v[i].z, v[i].w)));
    }
    __shared__ float redm[8], reds[8];
    for (int o = 16; o; o >>= 1) m = fmaxf(m, __shfl_xor_sync(0xffffffffu, m, o));
    if ((tid & 31) == 0) redm[tid >> 5] = m;
    __syncthreads();
    float M = redm[0];
#pragma unroll
    for (int w = 1; w < 8; w++) M = fmaxf(M, redm[w]);

    float s = 0.f;
#pragma unroll
    for (int i = 0; i < 4; i++) {
        v[i].x = __expf(v[i].x - M); v[i].y = __expf(v[i].y - M);
        v[i].z = __expf(v[i].z - M); v[i].w = __expf(v[i].w - M);
        s += v[i].x + v[i].y + v[i].z + v[i].w;
    }
    for (int o = 16; o; o >>= 1) s += __shfl_xor_sync(0xffffffffu, s, o);
    if ((tid & 31) == 0) reds[tid >> 5] = s;
    __syncthreads();
    float S = 0.f;
#pragma unroll
    for (int w = 0; w < 8; w++) S += reds[w];
    float inv = 1.0f / S;
#pragma unroll
    for (int i = 0; i < 4; i++) {
        v[i].x *= inv; v[i].y *= inv; v[i].z *= inv; v[i].w *= inv;
        p[tid + 256 * i] = v[i];
    }
}

// ============================================================================
// A = V P^T, out = x + A : out[b,c,i] = x[b,c,i] + sum_j v[b,c,j] P[b,i,j]
// grid: (NTOK/BN=32, CCH/BM=4, BATCH)
// ============================================================================
__global__ __launch_bounds__(256) void pv_kernel(const float* __restrict__ x,
                                                 float* __restrict__ out) {
    int b = blockIdx.z;
    const float* Vb = g_v + (size_t)b * CCH * NTOK;
    const float* Pb = g_s + (size_t)b * NTOK * NTOK;
    int n0 = blockIdx.x * BN, m0 = blockIdx.y * BM;

    __shared__ float As[BK][BM];
    __shared__ float Bs[BK][BN];
    int tid = threadIdx.x;
    int tx = tid & 15, ty = tid >> 4;

    float acc[8][8];
#pragma unroll
    for (int i = 0; i < 8; i++)
#pragma unroll
        for (int j = 0; j < 8; j++) acc[i][j] = 0.f;

    int lr = tid >> 1, lq = (tid & 1) * 4;  // row within tile, k quad

    for (int k0 = 0; k0 < NTOK; k0 += BK) {
        float4 a4 = *(const float4*)(Vb + (size_t)(m0 + lr) * NTOK + k0 + lq);
        As[lq + 0][lr] = a4.x; As[lq + 1][lr] = a4.y;
        As[lq + 2][lr] = a4.z; As[lq + 3][lr] = a4.w;
        float4 b4 = *(const float4*)(Pb + (size_t)(n0 + lr) * NTOK + k0 + lq);
        Bs[lq + 0][lr] = b4.x; Bs[lq + 1][lr] = b4.y;
        Bs[lq + 2][lr] = b4.z; Bs[lq + 3][lr] = b4.w;
        __syncthreads();
        GEMM_COMPUTE_BODY();
        __syncthreads();
    }

#pragma unroll
    for (int i = 0; i < 8; i++) {
        size_t off = ((size_t)b * CCH + m0 + ty * 8 + i) * NTOK + n0 + tx * 8;
        const float* xp = x + off;
        float* op = out + off;
        float4 x0 = *(const float4*)xp;
        float4 x1 = *(const float4*)(xp + 4);
        float4 o0 = { acc[i][0] + x0.x, acc[i][1] + x0.y, acc[i][2] + x0.z, acc[i][3] + x0.w };
        float4 o1 = { acc[i][4] + x1.x, acc[i][5] + x1.y, acc[i][6] + x1.z, acc[i][7] + x1.w };
        *(float4*)op = o0;
        *(float4*)(op + 4) = o1;
    }
}

// ============================================================================
extern "C" void kernel_launch(void* const* d_in, const int* in_sizes, int n_in,
                              void* d_out, int out_size) {
    const float* x   = (const float*)d_in[0];
    const float* gns = (const float*)d_in[1];
    const float* gnb = (const float*)d_in[2];
    const float* wq  = (const float*)d_in[3];
    const float* bq  = (const float*)d_in[4];
    const float* wk  = (const float*)d_in[5];
    const float* bk  = (const float*)d_in[6];
    const float* wv  = (const float*)d_in[7];
    const float* bv  = (const float*)d_in[8];
    float* out = (float*)d_out;
    (void)in_sizes; (void)n_in; (void)out_size;

    gn_kernel<<<BATCH * NG, 512>>>(x, gns, gnb);
    qkv_kernel<<<dim3(NTOK / BN, CCH / BM, BATCH * 3), 256>>>(wq, bq, wk, bk, wv, bv);
    s_kernel<<<dim3(NTOK / BN, NTOK / BM, BATCH), 256>>>();
    softmax_kernel<<<BATCH * NTOK, 256>>>();
    pv_kernel<<<dim3(NTOK / BN, CCH / BM, BATCH), 256>>>(x, out);
}

// round 6
// speedup vs baseline: 2.1655x; 2.1655x over previous
#include <cuda_runtime.h>
#include <cstdint>
#include <math.h>

#define CCH   512
#define NTOK  4096
#define BATCH 8
#define NG    32
#define CPG   16

// -------- scratch (device globals; no allocation allowed) --------
__device__ float g_h[(size_t)BATCH * CCH * NTOK];   // group-normed activations [b,c,n]
__device__ float g_q[(size_t)BATCH * CCH * NTOK];
__device__ float g_k[(size_t)BATCH * CCH * NTOK];
__device__ float g_v[(size_t)BATCH * CCH * NTOK];
__device__ float g_s[(size_t)BATCH * NTOK * NTOK];  // attention logits / probs (in-place softmax)

#define MMA_TF32(c0, c1, c2, c3, a0, a1, a2, a3, b0, b1)                      \
    asm volatile("mma.sync.aligned.m16n8k8.row.col.f32.tf32.tf32.f32 "        \
                 "{%0,%1,%2,%3}, {%4,%5,%6,%7}, {%8,%9}, {%0,%1,%2,%3};"      \
                 : "+f"(c0), "+f"(c1), "+f"(c2), "+f"(c3)                     \
                 : "r"(a0), "r"(a1), "r"(a2), "r"(a3), "r"(b0), "r"(b1))

// ============================================================================
// GroupNorm: one block per (batch, group). 16 channels x 4096 = 65536 floats.
// (verbatim from the passing Round-1 kernel)
// ============================================================================
__global__ __launch_bounds__(512) void gn_kernel(const float* __restrict__ x,
                                                 const float* __restrict__ sc,
                                                 const float* __restrict__ bi) {
    int bg = blockIdx.x;  // b*32 + g
    const float4* xp = (const float4*)(x + (size_t)bg * CPG * NTOK);
    float4* hp = (float4*)(g_h + (size_t)bg * CPG * NTOK);
    int tid = threadIdx.x;

    const int TOT4 = CPG * NTOK / 4;  // 16384 float4
    float s = 0.f, ss = 0.f;
    for (int i = tid; i < TOT4; i += 512) {
        float4 v = xp[i];
        s  += v.x + v.y + v.z + v.w;
        ss += v.x * v.x + v.y * v.y + v.z * v.z + v.w * v.w;
    }
    __shared__ float rs[16], rss[16];
    for (int o = 16; o; o >>= 1) {
        s  += __shfl_xor_sync(0xffffffffu, s, o);
        ss += __shfl_xor_sync(0xffffffffu, ss, o);
    }
    if ((tid & 31) == 0) { rs[tid >> 5] = s; rss[tid >> 5] = ss; }
    __syncthreads();
    __shared__ float mean_s, rstd_s;
    if (tid == 0) {
        float S = 0.f, SS = 0.f;
        for (int w = 0; w < 16; w++) { S += rs[w]; SS += rss[w]; }
        float inv_n = 1.0f / (float)(CPG * NTOK);
        float mean = S * inv_n;
        float var  = SS * inv_n - mean * mean;
        mean_s = mean;
        rstd_s = rsqrtf(var + 1e-6f);
    }
    __syncthreads();
    float mean = mean_s, rstd = rstd_s;
    int g = bg & (NG - 1);

    __shared__ float a_s[CPG], b_s[CPG];
    if (tid < CPG) {
        float a = rstd * sc[g * CPG + tid];
        a_s[tid] = a;
        b_s[tid] = bi[g * CPG + tid] - mean * a;
    }
    __syncthreads();
    for (int i = tid; i < TOT4; i += 512) {
        int cl = i >> 10;
        float a = a_s[cl], b2 = b_s[cl];
        float4 v = xp[i];
        v.x = v.x * a + b2; v.y = v.y * a + b2; v.z = v.z * a + b2; v.w = v.w * a + b2;
        hp[i] = v;
    }
}

// ============================================================================
// GEMM tile config: 128x128x8, 256 threads (8 warps as 2x4), warp tile 64x32.
// Smem is k-major As[k][m], Bs[k][n] (R1 layout), rows padded to 136 floats.
// Inner compute: mma.sync.m16n8k8 tf32 (fragment source = k-major smem).
// ============================================================================
#define BM 128
#define BN 128
#define BK 8
#define LDP 136   // padded smem row length in floats

// fragment gather + 16 MMAs for one BK=8 slab
#define MMA_BODY()                                                            \
    do {                                                                      \
        uint32_t af0[4], af1[4], af2[4], af3[4];                              \
        _Pragma("unroll")                                                     \
        for (int mt = 0; mt < 4; mt++) {                                      \
            const int r = wm * 64 + mt * 16 + g;                              \
            af0[mt] = __float_as_uint(As[t][r]);                              \
            af1[mt] = __float_as_uint(As[t][r + 8]);                          \
            af2[mt] = __float_as_uint(As[t + 4][r]);                          \
            af3[mt] = __float_as_uint(As[t + 4][r + 8]);                      \
        }                                                                     \
        _Pragma("unroll")                                                     \
        for (int nt = 0; nt < 4; nt++) {                                      \
            const int q = wn * 32 + nt * 8 + g;                               \
            uint32_t b0 = __float_as_uint(Bs[t][q]);                          \
            uint32_t b1 = __float_as_uint(Bs[t + 4][q]);                      \
            _Pragma("unroll")                                                 \
            for (int mt = 0; mt < 4; mt++)                                    \
                MMA_TF32(acc[mt][nt][0], acc[mt][nt][1],                      \
                         acc[mt][nt][2], acc[mt][nt][3],                      \
                         af0[mt], af1[mt], af2[mt], af3[mt], b0, b1);         \
        }                                                                     \
    } while (0)

#define DECL_MMA_STATE()                                                      \
    const int tid = threadIdx.x;                                              \
    const int wid = tid >> 5, lane = tid & 31;                                \
    const int wm = wid & 1, wn = wid >> 1;                                    \
    const int g = lane >> 2, t = lane & 3;                                    \
    float acc[4][4][4];                                                       \
    _Pragma("unroll")                                                         \
    for (int mt = 0; mt < 4; mt++)                                            \
        _Pragma("unroll")                                                     \
        for (int nt = 0; nt < 4; nt++) {                                      \
            acc[mt][nt][0] = 0.f; acc[mt][nt][1] = 0.f;                       \
            acc[mt][nt][2] = 0.f; acc[mt][nt][3] = 0.f;                       \
        }

// ============================================================================
// QKV projection: out[b,o,n] = bias[o] + sum_c W[o,c] * h[b,c,n]
// grid: (NTOK/BN=32, CCH/BM=4, BATCH*3=24)
// ============================================================================
__global__ __launch_bounds__(256) void qkv_kernel(
    const float* __restrict__ wq, const float* __restrict__ bq,
    const float* __restrict__ wk, const float* __restrict__ bk,
    const float* __restrict__ wv, const float* __restrict__ bv) {
    int z = blockIdx.z;
    int b = z / 3, wsel = z - 3 * b;
    const float* W    = (wsel == 0) ? wq : (wsel == 1) ? wk : wv;
    const float* bias = (wsel == 0) ? bq : (wsel == 1) ? bk : bv;
    float* outg       = (wsel == 0) ? g_q : (wsel == 1) ? g_k : g_v;

    const float* Hb = g_h + (size_t)b * CCH * NTOK;
    float* Ob = outg + (size_t)b * CCH * NTOK;
    int n0 = blockIdx.x * BN, m0 = blockIdx.y * BM;

    __shared__ float As[BK][LDP];
    __shared__ float Bs[BK][LDP];
    DECL_MMA_STATE();

    int am = tid >> 1, ak = (tid & 1) * 4;     // A: W[m0+am, k0+ak..+3]
    int bk_ = tid >> 5, bn_ = (tid & 31) * 4;  // B: h[k0+bk_, n0+bn_..+3]

    for (int k0 = 0; k0 < CCH; k0 += BK) {
        float4 a4 = *(const float4*)(W + (size_t)(m0 + am) * CCH + k0 + ak);
        As[ak + 0][am] = a4.x; As[ak + 1][am] = a4.y;
        As[ak + 2][am] = a4.z; As[ak + 3][am] = a4.w;
        *(float4*)&Bs[bk_][bn_] =
            *(const float4*)(Hb + (size_t)(k0 + bk_) * NTOK + n0 + bn_);
        __syncthreads();
        MMA_BODY();
        __syncthreads();
    }

#pragma unroll
    for (int mt = 0; mt < 4; mt++) {
        const int r0 = m0 + wm * 64 + mt * 16 + g;
        const int r1 = r0 + 8;
        const float bv0 = bias[r0], bv1 = bias[r1];
#pragma unroll
        for (int nt = 0; nt < 4; nt++) {
            const int col = n0 + wn * 32 + nt * 8 + 2 * t;
            float2 lo, hi;
            lo.x = acc[mt][nt][0] + bv0; lo.y = acc[mt][nt][1] + bv0;
            hi.x = acc[mt][nt][2] + bv1; hi.y = acc[mt][nt][3] + bv1;
            *(float2*)(Ob + (size_t)r0 * NTOK + col) = lo;
            *(float2*)(Ob + (size_t)r1 * NTOK + col) = hi;
        }
    }
}

// ============================================================================
// S = scale * Q^T K : S[b,i,j] = scale * sum_c q[b,c,i] k[b,c,j]
// grid: (NTOK/BN=32, NTOK/BM=32, BATCH)
// ============================================================================
__global__ __launch_bounds__(256) void s_kernel() {
    int b = blockIdx.z;
    const float* Qb = g_q + (size_t)b * CCH * NTOK;
    const float* Kb = g_k + (size_t)b * CCH * NTOK;
    float* Sb = g_s + (size_t)b * NTOK * NTOK;
    int n0 = blockIdx.x * BN, m0 = blockIdx.y * BM;

    __shared__ float As[BK][LDP];
    __shared__ float Bs[BK][LDP];
    DECL_MMA_STATE();

    int lk = tid >> 5, lm = (tid & 31) * 4;

    for (int k0 = 0; k0 < CCH; k0 += BK) {
        *(float4*)&As[lk][lm] = *(const float4*)(Qb + (size_t)(k0 + lk) * NTOK + m0 + lm);
        *(float4*)&Bs[lk][lm] = *(const float4*)(Kb + (size_t)(k0 + lk) * NTOK + n0 + lm);
        __syncthreads();
        MMA_BODY();
        __syncthreads();
    }

    const float scale = 0.044194173824159216f;  // 512^-0.5
#pragma unroll
    for (int mt = 0; mt < 4; mt++) {
        const int r0 = m0 + wm * 64 + mt * 16 + g;
        const int r1 = r0 + 8;
#pragma unroll
        for (int nt = 0; nt < 4; nt++) {
            const int col = n0 + wn * 32 + nt * 8 + 2 * t;
            float2 lo, hi;
            lo.x = acc[mt][nt][0] * scale; lo.y = acc[mt][nt][1] * scale;
            hi.x = acc[mt][nt][2] * scale; hi.y = acc[mt][nt][3] * scale;
            *(float2*)(Sb + (size_t)r0 * NTOK + col) = lo;
            *(float2*)(Sb + (size_t)r1 * NTOK + col) = hi;
        }
    }
}

// ============================================================================
// Row softmax over g_s, in place. One block per row (verbatim from Round 1).
// ============================================================================
__global__ __launch_bounds__(256) void softmax_kernel() {
    size_t row = blockIdx.x;
    float4* p = (float4*)(g_s + row * NTOK);
    int tid = threadIdx.x;

    float4 v[4];
    float m = -1e30f;
#pragma unroll
    for (int i = 0; i < 4; i++) {
        v[i] = p[tid + 256 * i];
        m = fmaxf(m, fmaxf(fmaxf(v[i].x, v[i].y), fmaxf(v[i].z, v[i].w)));
    }
    __shared__ float redm[8], reds[8];
    for (int o = 16; o; o >>= 1) m = fmaxf(m, __shfl_xor_sync(0xffffffffu, m, o));
    if ((tid & 31) == 0) redm[tid >> 5] = m;
    __syncthreads();
    float M = redm[0];
#pragma unroll
    for (int w = 1; w < 8; w++) M = fmaxf(M, redm[w]);

    float s = 0.f;
#pragma unroll
    for (int i = 0; i < 4; i++) {
        v[i].x = __expf(v[i].x - M); v[i].y = __expf(v[i].y - M);
        v[i].z = __expf(v[i].z - M); v[i].w = __expf(v[i].w - M);
        s += v[i].x + v[i].y + v[i].z + v[i].w;
    }
    for (int o = 16; o; o >>= 1) s += __shfl_xor_sync(0xffffffffu, s, o);
    if ((tid & 31) == 0) reds[tid >> 5] = s;
    __syncthreads();
    float S = 0.f;
#pragma unroll
    for (int w = 0; w < 8; w++) S += reds[w];
    float inv = 1.0f / S;
#pragma unroll
    for (int i = 0; i < 4; i++) {
        v[i].x *= inv; v[i].y *= inv; v[i].z *= inv; v[i].w *= inv;
        p[tid + 256 * i] = v[i];
    }
}

// ============================================================================
// A = V P^T, out = x + A : out[b,c,i] = x[b,c,i] + sum_j v[b,c,j] P[b,i,j]
// grid: (NTOK/BN=32, CCH/BM=4, BATCH)
// ============================================================================
__global__ __launch_bounds__(256) void pv_kernel(const float* __restrict__ x,
                                                 float* __restrict__ out) {
    int b = blockIdx.z;
    const float* Vb = g_v + (size_t)b * CCH * NTOK;
    const float* Pb = g_s + (size_t)b * NTOK * NTOK;
    int n0 = blockIdx.x * BN, m0 = blockIdx.y * BM;

    __shared__ float As[BK][LDP];
    __shared__ float Bs[BK][LDP];
    DECL_MMA_STATE();

    int lr = tid >> 1, lq = (tid & 1) * 4;  // row within tile, k quad

    for (int k0 = 0; k0 < NTOK; k0 += BK) {
        float4 a4 = *(const float4*)(Vb + (size_t)(m0 + lr) * NTOK + k0 + lq);
        As[lq + 0][lr] = a4.x; As[lq + 1][lr] = a4.y;
        As[lq + 2][lr] = a4.z; As[lq + 3][lr] = a4.w;
        float4 b4 = *(const float4*)(Pb + (size_t)(n0 + lr) * NTOK + k0 + lq);
        Bs[lq + 0][lr] = b4.x; Bs[lq + 1][lr] = b4.y;
        Bs[lq + 2][lr] = b4.z; Bs[lq + 3][lr] = b4.w;
        __syncthreads();
        MMA_BODY();
        __syncthreads();
    }

#pragma unroll
    for (int mt = 0; mt < 4; mt++) {
        const int r0 = m0 + wm * 64 + mt * 16 + g;
        const int r1 = r0 + 8;
#pragma unroll
        for (int nt = 0; nt < 4; nt++) {
            const int col = n0 + wn * 32 + nt * 8 + 2 * t;
            size_t o0 = ((size_t)b * CCH + r0) * NTOK + col;
            size_t o1 = ((size_t)b * CCH + r1) * NTOK + col;
            float2 x0 = *(const float2*)(x + o0);
            float2 x1 = *(const float2*)(x + o1);
            float2 lo, hi;
            lo.x = acc[mt][nt][0] + x0.x; lo.y = acc[mt][nt][1] + x0.y;
            hi.x = acc[mt][nt][2] + x1.x; hi.y = acc[mt][nt][3] + x1.y;
            *(float2*)(out + o0) = lo;
            *(float2*)(out + o1) = hi;
        }
    }
}

// ============================================================================
extern "C" void kernel_launch(void* const* d_in, const int* in_sizes, int n_in,
                              void* d_out, int out_size) {
    const float* x   = (const float*)d_in[0];
    const float* gns = (const float*)d_in[1];
    const float* gnb = (const float*)d_in[2];
    const float* wq  = (const float*)d_in[3];
    const float* bq  = (const float*)d_in[4];
    const float* wk  = (const float*)d_in[5];
    const float* bk  = (const float*)d_in[6];
    const float* wv  = (const float*)d_in[7];
    const float* bv  = (const float*)d_in[8];
    float* out = (float*)d_out;
    (void)in_sizes; (void)n_in; (void)out_size;

    gn_kernel<<<BATCH * NG, 512>>>(x, gns, gnb);
    qkv_kernel<<<dim3(NTOK / BN, CCH / BM, BATCH * 3), 256>>>(wq, bq, wk, bk, wv, bv);
    s_kernel<<<dim3(NTOK / BN, NTOK / BM, BATCH), 256>>>();
    softmax_kernel<<<BATCH * NTOK, 256>>>();
    pv_kernel<<<dim3(NTOK / BN, CCH / BM, BATCH), 256>>>(x, out);
}

// round 7
// speedup vs baseline: 3.1394x; 1.4497x over previous
#include <cuda_runtime.h>
#include <cstdint>
#include <math.h>

#define CCH   512
#define NTOK  4096
#define BATCH 8
#define NG    32
#define CPG   16

// -------- scratch (device globals; no allocation allowed) --------
__device__ float g_h[(size_t)BATCH * CCH * NTOK];   // group-normed activations [b,c,n]
__device__ float g_q[(size_t)BATCH * CCH * NTOK];
__device__ float g_k[(size_t)BATCH * CCH * NTOK];
__device__ float g_v[(size_t)BATCH * CCH * NTOK];
__device__ float g_s[(size_t)BATCH * NTOK * NTOK];  // attention logits / probs (in-place softmax)

#define MMA_TF32(c0, c1, c2, c3, a0, a1, a2, a3, b0, b1)                      \
    asm volatile("mma.sync.aligned.m16n8k8.row.col.f32.tf32.tf32.f32 "        \
                 "{%0,%1,%2,%3}, {%4,%5,%6,%7}, {%8,%9}, {%0,%1,%2,%3};"      \
                 : "+f"(c0), "+f"(c1), "+f"(c2), "+f"(c3)                     \
                 : "r"(a0), "r"(a1), "r"(a2), "r"(a3), "r"(b0), "r"(b1))

// ============================================================================
// GroupNorm: one block per (batch, group). (verbatim from passing R6)
// ============================================================================
__global__ __launch_bounds__(512) void gn_kernel(const float* __restrict__ x,
                                                 const float* __restrict__ sc,
                                                 const float* __restrict__ bi) {
    int bg = blockIdx.x;  // b*32 + g
    const float4* xp = (const float4*)(x + (size_t)bg * CPG * NTOK);
    float4* hp = (float4*)(g_h + (size_t)bg * CPG * NTOK);
    int tid = threadIdx.x;

    const int TOT4 = CPG * NTOK / 4;
    float s = 0.f, ss = 0.f;
    for (int i = tid; i < TOT4; i += 512) {
        float4 v = xp[i];
        s  += v.x + v.y + v.z + v.w;
        ss += v.x * v.x + v.y * v.y + v.z * v.z + v.w * v.w;
    }
    __shared__ float rs[16], rss[16];
    for (int o = 16; o; o >>= 1) {
        s  += __shfl_xor_sync(0xffffffffu, s, o);
        ss += __shfl_xor_sync(0xffffffffu, ss, o);
    }
    if ((tid & 31) == 0) { rs[tid >> 5] = s; rss[tid >> 5] = ss; }
    __syncthreads();
    __shared__ float mean_s, rstd_s;
    if (tid == 0) {
        float S = 0.f, SS = 0.f;
        for (int w = 0; w < 16; w++) { S += rs[w]; SS += rss[w]; }
        float inv_n = 1.0f / (float)(CPG * NTOK);
        float mean = S * inv_n;
        float var  = SS * inv_n - mean * mean;
        mean_s = mean;
        rstd_s = rsqrtf(var + 1e-6f);
    }
    __syncthreads();
    float mean = mean_s, rstd = rstd_s;
    int g = bg & (NG - 1);

    __shared__ float a_s[CPG], b_s[CPG];
    if (tid < CPG) {
        float a = rstd * sc[g * CPG + tid];
        a_s[tid] = a;
        b_s[tid] = bi[g * CPG + tid] - mean * a;
    }
    __syncthreads();
    for (int i = tid; i < TOT4; i += 512) {
        int cl = i >> 10;
        float a = a_s[cl], b2 = b_s[cl];
        float4 v = xp[i];
        v.x = v.x * a + b2; v.y = v.y * a + b2; v.z = v.z * a + b2; v.w = v.w * a + b2;
        hp[i] = v;
    }
}

// ============================================================================
// GEMM config: 128x128x16 CTA tile, 256 threads (2x4 warps), warp tile 64x32.
// Double-buffered static smem, register prefetch, one sync per slab.
// k-major tiles [16][136] for k-major gmem operands; m-major tiles [128][20]
// for m-major gmem operands. All loaders are direct float4 copies.
// ============================================================================
#define BM 128
#define BN 128
#define BK 16
#define LDK 136   // padded k-major row (floats)
#define LDM 20    // padded m-major row (floats)

#define DECL_MMA_STATE()                                                      \
    const int tid = threadIdx.x;                                              \
    const int wid = tid >> 5, lane = tid & 31;                                \
    const int wm = wid & 1, wn = wid >> 1;                                    \
    const int g = lane >> 2, t = lane & 3;                                    \
    float acc[4][4][4];                                                       \
    _Pragma("unroll")                                                         \
    for (int mt = 0; mt < 4; mt++)                                            \
        _Pragma("unroll")                                                     \
        for (int nt = 0; nt < 4; nt++) {                                      \
            acc[mt][nt][0] = 0.f; acc[mt][nt][1] = 0.f;                       \
            acc[mt][nt][2] = 0.f; acc[mt][nt][3] = 0.f;                       \
        }

// 16 MMAs for one 8-deep k-step; A fragments passed in
#define MMA_KSTEP(B0EXPR, B1EXPR)                                             \
    _Pragma("unroll")                                                         \
    for (int nt = 0; nt < 4; nt++) {                                          \
        const int q = wn * 32 + nt * 8 + g;                                   \
        uint32_t b0 = __float_as_uint(B0EXPR);                                \
        uint32_t b1 = __float_as_uint(B1EXPR);                                \
        _Pragma("unroll")                                                     \
        for (int mt = 0; mt < 4; mt++)                                        \
            MMA_TF32(acc[mt][nt][0], acc[mt][nt][1],                          \
                     acc[mt][nt][2], acc[mt][nt][3],                          \
                     af0[mt], af1[mt], af2[mt], af3[mt], b0, b1);             \
    }

// ============================================================================
// QKV projection: out[b,o,n] = bias[o] + sum_c W[o,c] * h[b,c,n]
// A = W (m-major), B = h (k-major). grid (32, 4, 24)
// ============================================================================
__global__ __launch_bounds__(256) void qkv_kernel(
    const float* __restrict__ wq, const float* __restrict__ bq,
    const float* __restrict__ wk, const float* __restrict__ bk,
    const float* __restrict__ wv, const float* __restrict__ bv) {
    int z = blockIdx.z;
    int b = z / 3, wsel = z - 3 * b;
    const float* W    = (wsel == 0) ? wq : (wsel == 1) ? wk : wv;
    const float* bias = (wsel == 0) ? bq : (wsel == 1) ? bk : bv;
    float* outg       = (wsel == 0) ? g_q : (wsel == 1) ? g_k : g_v;

    const float* Hb = g_h + (size_t)b * CCH * NTOK;
    float* Ob = outg + (size_t)b * CCH * NTOK;
    int n0 = blockIdx.x * BN, m0 = blockIdx.y * BM;

    __shared__ float Asm[2][BM][LDM];
    __shared__ float Bs[2][BK][LDK];
    DECL_MMA_STATE();

    const int arow = tid >> 2, akq = (tid & 3) * 4;
    const int brow = tid >> 5, bcol = (tid & 31) * 4;
    const float* Ag = W + (size_t)(m0 + arow) * CCH + akq;
    const float* Bg = Hb + (size_t)brow * NTOK + n0 + bcol;

    *(float4*)&Asm[0][arow][akq]      = *(const float4*)(Ag);
    *(float4*)&Asm[0][arow + 64][akq] = *(const float4*)(Ag + (size_t)64 * CCH);
    *(float4*)&Bs[0][brow][bcol]      = *(const float4*)(Bg);
    *(float4*)&Bs[0][brow + 8][bcol]  = *(const float4*)(Bg + (size_t)8 * NTOK);
    __syncthreads();

    const int NC = CCH / BK;
    float4 pa0, pa1, pb0, pb1;
    for (int c = 0; c < NC; c++) {
        const int s = c & 1;
        if (c + 1 < NC) {
            const float* Ap = Ag + (c + 1) * BK;
            const float* Bp = Bg + (size_t)(c + 1) * BK * NTOK;
            pa0 = *(const float4*)(Ap);
            pa1 = *(const float4*)(Ap + (size_t)64 * CCH);
            pb0 = *(const float4*)(Bp);
            pb1 = *(const float4*)(Bp + (size_t)8 * NTOK);
        }
#pragma unroll
        for (int kk = 0; kk < 2; kk++) {
            const int te = kk * 8 + t;
            uint32_t af0[4], af1[4], af2[4], af3[4];
#pragma unroll
            for (int mt = 0; mt < 4; mt++) {
                const int r = wm * 64 + mt * 16 + g;
                af0[mt] = __float_as_uint(Asm[s][r][te]);
                af1[mt] = __float_as_uint(Asm[s][r + 8][te]);
                af2[mt] = __float_as_uint(Asm[s][r][te + 4]);
                af3[mt] = __float_as_uint(Asm[s][r + 8][te + 4]);
            }
            MMA_KSTEP(Bs[s][te][q], Bs[s][te + 4][q]);
        }
        if (c + 1 < NC) {
            const int ns = 1 - s;
            *(float4*)&Asm[ns][arow][akq]      = pa0;
            *(float4*)&Asm[ns][arow + 64][akq] = pa1;
            *(float4*)&Bs[ns][brow][bcol]      = pb0;
            *(float4*)&Bs[ns][brow + 8][bcol]  = pb1;
            __syncthreads();
        }
    }

#pragma unroll
    for (int mt = 0; mt < 4; mt++) {
        const int r0 = m0 + wm * 64 + mt * 16 + g;
        const int r1 = r0 + 8;
        const float bv0 = bias[r0], bv1 = bias[r1];
#pragma unroll
        for (int nt = 0; nt < 4; nt++) {
            const int col = n0 + wn * 32 + nt * 8 + 2 * t;
            float2 lo, hi;
            lo.x = acc[mt][nt][0] + bv0; lo.y = acc[mt][nt][1] + bv0;
            hi.x = acc[mt][nt][2] + bv1; hi.y = acc[mt][nt][3] + bv1;
            *(float2*)(Ob + (size_t)r0 * NTOK + col) = lo;
            *(float2*)(Ob + (size_t)r1 * NTOK + col) = hi;
        }
    }
}

// ============================================================================
// S = scale * Q^T K. Both operands k-major. grid (32, 32, 8)
// ============================================================================
__global__ __launch_bounds__(256) void s_kernel() {
    int b = blockIdx.z;
    const float* Qb = g_q + (size_t)b * CCH * NTOK;
    const float* Kb = g_k + (size_t)b * CCH * NTOK;
    float* Sb = g_s + (size_t)b * NTOK * NTOK;
    int n0 = blockIdx.x * BN, m0 = blockIdx.y * BM;

    __shared__ float As[2][BK][LDK];
    __shared__ float Bs[2][BK][LDK];
    DECL_MMA_STATE();

    const int lrow = tid >> 5, lcol = (tid & 31) * 4;
    const float* Ag = Qb + (size_t)lrow * NTOK + m0 + lcol;
    const float* Bg = Kb + (size_t)lrow * NTOK + n0 + lcol;

    *(float4*)&As[0][lrow][lcol]     = *(const float4*)(Ag);
    *(float4*)&As[0][lrow + 8][lcol] = *(const float4*)(Ag + (size_t)8 * NTOK);
    *(float4*)&Bs[0][lrow][lcol]     = *(const float4*)(Bg);
    *(float4*)&Bs[0][lrow + 8][lcol] = *(const float4*)(Bg + (size_t)8 * NTOK);
    __syncthreads();

    const int NC = CCH / BK;
    float4 pa0, pa1, pb0, pb1;
    for (int c = 0; c < NC; c++) {
        const int s = c & 1;
        if (c + 1 < NC) {
            const float* Ap = Ag + (size_t)(c + 1) * BK * NTOK;
            const float* Bp = Bg + (size_t)(c + 1) * BK * NTOK;
            pa0 = *(const float4*)(Ap);
            pa1 = *(const float4*)(Ap + (size_t)8 * NTOK);
            pb0 = *(const float4*)(Bp);
            pb1 = *(const float4*)(Bp + (size_t)8 * NTOK);
        }
#pragma unroll
        for (int kk = 0; kk < 2; kk++) {
            const int te = kk * 8 + t;
            uint32_t af0[4], af1[4], af2[4], af3[4];
#pragma unroll
            for (int mt = 0; mt < 4; mt++) {
                const int r = wm * 64 + mt * 16 + g;
                af0[mt] = __float_as_uint(As[s][te][r]);
                af1[mt] = __float_as_uint(As[s][te][r + 8]);
                af2[mt] = __float_as_uint(As[s][te + 4][r]);
                af3[mt] = __float_as_uint(As[s][te + 4][r + 8]);
            }
            MMA_KSTEP(Bs[s][te][q], Bs[s][te + 4][q]);
        }
        if (c + 1 < NC) {
            const int ns = 1 - s;
            *(float4*)&As[ns][lrow][lcol]     = pa0;
            *(float4*)&As[ns][lrow + 8][lcol] = pa1;
            *(float4*)&Bs[ns][lrow][lcol]     = pb0;
            *(float4*)&Bs[ns][lrow + 8][lcol] = pb1;
            __syncthreads();
        }
    }

    const float scale = 0.044194173824159216f;  // 512^-0.5
#pragma unroll
    for (int mt = 0; mt < 4; mt++) {
        const int r0 = m0 + wm * 64 + mt * 16 + g;
        const int r1 = r0 + 8;
#pragma unroll
        for (int nt = 0; nt < 4; nt++) {
            const int col = n0 + wn * 32 + nt * 8 + 2 * t;
            float2 lo, hi;
            lo.x = acc[mt][nt][0] * scale; lo.y = acc[mt][nt][1] * scale;
            hi.x = acc[mt][nt][2] * scale; hi.y = acc[mt][nt][3] * scale;
            *(float2*)(Sb + (size_t)r0 * NTOK + col) = lo;
            *(float2*)(Sb + (size_t)r1 * NTOK + col) = hi;
        }
    }
}

// ============================================================================
// Row softmax over g_s, in place. (verbatim from passing R6)
// ============================================================================
__global__ __launch_bounds__(256) void softmax_kernel() {
    size_t row = blockIdx.x;
    float4* p = (float4*)(g_s + row * NTOK);
    int tid = threadIdx.x;

    float4 v[4];
    float m = -1e30f;
#pragma unroll
    for (int i = 0; i < 4; i++) {
        v[i] = p[tid + 256 * i];
        m = fmaxf(m, fmaxf(fmaxf(v[i].x, v[i].y), fmaxf(v[i].z, v[i].w)));
    }
    __shared__ float redm[8], reds[8];
    for (int o = 16; o; o >>= 1) m = fmaxf(m, __shfl_xor_sync(0xffffffffu, m, o));
    if ((tid & 31) == 0) redm[tid >> 5] = m;
    __syncthreads();
    float M = redm[0];
#pragma unroll
    for (int w = 1; w < 8; w++) M = fmaxf(M, redm[w]);

    float s = 0.f;
#pragma unroll
    for (int i = 0; i < 4; i++) {
        v[i].x = __expf(v[i].x - M); v[i].y = __expf(v[i].y - M);
        v[i].z = __expf(v[i].z - M); v[i].w = __expf(v[i].w - M);
        s += v[i].x + v[i].y + v[i].z + v[i].w;
    }
    for (int o = 16; o; o >>= 1) s += __shfl_xor_sync(0xffffffffu, s, o);
    if ((tid & 31) == 0) reds[tid >> 5] = s;
    __syncthreads();
    float S = 0.f;
#pragma unroll
    for (int w = 0; w < 8; w++) S += reds[w];
    float inv = 1.0f / S;
#pragma unroll
    for (int i = 0; i < 4; i++) {
        v[i].x *= inv; v[i].y *= inv; v[i].z *= inv; v[i].w *= inv;
        p[tid + 256 * i] = v[i];
    }
}

// ============================================================================
// A = V P^T, out = x + A. A = V (m-major), B = P (n-major). grid (32, 4, 8)
// ============================================================================
__global__ __launch_bounds__(256) void pv_kernel(const float* __restrict__ x,
                                                 float* __restrict__ out) {
    int b = blockIdx.z;
    const float* Vb = g_v + (size_t)b * CCH * NTOK;
    const float* Pb = g_s + (size_t)b * NTOK * NTOK;
    int n0 = blockIdx.x * BN, m0 = blockIdx.y * BM;

    __shared__ float Asm[2][BM][LDM];
    __shared__ float Bsn[2][BN][LDM];
    DECL_MMA_STATE();

    const int arow = tid >> 2, akq = (tid & 3) * 4;
    const float* Ag = Vb + (size_t)(m0 + arow) * NTOK + akq;
    const float* Bg = Pb + (size_t)(n0 + arow) * NTOK + akq;

    *(float4*)&Asm[0][arow][akq]      = *(const float4*)(Ag);
    *(float4*)&Asm[0][arow + 64][akq] = *(const float4*)(Ag + (size_t)64 * NTOK);
    *(float4*)&Bsn[0][arow][akq]      = *(const float4*)(Bg);
    *(float4*)&Bsn[0][arow + 64][akq] = *(const float4*)(Bg + (size_t)64 * NTOK);
    __syncthreads();

    const int NC = NTOK / BK;
    float4 pa0, pa1, pb0, pb1;
    for (int c = 0; c < NC; c++) {
        const int s = c & 1;
        if (c + 1 < NC) {
            const float* Ap = Ag + (c + 1) * BK;
            const float* Bp = Bg + (c + 1) * BK;
            pa0 = *(const float4*)(Ap);
            pa1 = *(const float4*)(Ap + (size_t)64 * NTOK);
            pb0 = *(const float4*)(Bp);
            pb1 = *(const float4*)(Bp + (size_t)64 * NTOK);
        }
#pragma unroll
        for (int kk = 0; kk < 2; kk++) {
            const int te = kk * 8 + t;
            uint32_t af0[4], af1[4], af2[4], af3[4];
#pragma unroll
            for (int mt = 0; mt < 4; mt++) {
                const int r = wm * 64 + mt * 16 + g;
                af0[mt] = __float_as_uint(Asm[s][r][te]);
                af1[mt] = __float_as_uint(Asm[s][r + 8][te]);
                af2[mt] = __float_as_uint(Asm[s][r][te + 4]);
                af3[mt] = __float_as_uint(Asm[s][r + 8][te + 4]);
            }
            MMA_KSTEP(Bsn[s][q][te], Bsn[s][q][te + 4]);
        }
        if (c + 1 < NC) {
            const int ns = 1 - s;
            *(float4*)&Asm[ns][arow][akq]      = pa0;
            *(float4*)&Asm[ns][arow + 64][akq] = pa1;
            *(float4*)&Bsn[ns][arow][akq]      = pb0;
            *(float4*)&Bsn[ns][arow + 64][akq] = pb1;
            __syncthreads();
        }
    }

#pragma unroll
    for (int mt = 0; mt < 4; mt++) {
        const int r0 = m0 + wm * 64 + mt * 16 + g;
        const int r1 = r0 + 8;
#pragma unroll
        for (int nt = 0; nt < 4; nt++) {
            const int col = n0 + wn * 32 + nt * 8 + 2 * t;
            size_t o0 = ((size_t)b * CCH + r0) * NTOK + col;
            size_t o1 = ((size_t)b * CCH + r1) * NTOK + col;
            float2 x0 = *(const float2*)(x + o0);
            float2 x1 = *(const float2*)(x + o1);
            float2 lo, hi;
            lo.x = acc[mt][nt][0] + x0.x; lo.y = acc[mt][nt][1] + x0.y;
            hi.x = acc[mt][nt][2] + x1.x; hi.y = acc[mt][nt][3] + x1.y;
            *(float2*)(out + o0) = lo;
            *(float2*)(out + o1) = hi;
        }
    }
}

// ============================================================================
extern "C" void kernel_launch(void* const* d_in, const int* in_sizes, int n_in,
                              void* d_out, int out_size) {
    const float* x   = (const float*)d_in[0];
    const float* gns = (const float*)d_in[1];
    const float* gnb = (const float*)d_in[2];
    const float* wq  = (const float*)d_in[3];
    const float* bq  = (const float*)d_in[4];
    const float* wk  = (const float*)d_in[5];
    const float* bk  = (const float*)d_in[6];
    const float* wv  = (const float*)d_in[7];
    const float* bv  = (const float*)d_in[8];
    float* out = (float*)d_out;
    (void)in_sizes; (void)n_in; (void)out_size;

    gn_kernel<<<BATCH * NG, 512>>>(x, gns, gnb);
    qkv_kernel<<<dim3(NTOK / BN, CCH / BM, BATCH * 3), 256>>>(wq, bq, wk, bk, wv, bv);
    s_kernel<<<dim3(NTOK / BN, NTOK / BM, BATCH), 256>>>();
    softmax_kernel<<<BATCH * NTOK, 256>>>();
    pv_kernel<<<dim3(NTOK / BN, CCH / BM, BATCH), 256>>>(x, out);
}

// round 8
// speedup vs baseline: 3.3616x; 1.0708x over previous
#include <cuda_runtime.h>
#include <cstdint>
#include <math.h>

#define CCH   512
#define NTOK  4096
#define BATCH 8
#define NG    32
#define CPG   16

// -------- scratch (device globals; no allocation allowed) --------
__device__ float g_h[(size_t)BATCH * CCH * NTOK];   // group-normed activations [b,c,n]
__device__ float g_q[(size_t)BATCH * CCH * NTOK];
__device__ float g_k[(size_t)BATCH * CCH * NTOK];
__device__ float g_v[(size_t)BATCH * CCH * NTOK];
__device__ float g_s[(size_t)BATCH * NTOK * NTOK];  // attention logits / probs (in-place softmax)

#define MMA_TF32(c0, c1, c2, c3, a0, a1, a2, a3, b0, b1)                      \
    asm volatile("mma.sync.aligned.m16n8k8.row.col.f32.tf32.tf32.f32 "        \
                 "{%0,%1,%2,%3}, {%4,%5,%6,%7}, {%8,%9}, {%0,%1,%2,%3};"      \
                 : "+f"(c0), "+f"(c1), "+f"(c2), "+f"(c3)                     \
                 : "r"(a0), "r"(a1), "r"(a2), "r"(a3), "r"(b0), "r"(b1))

// ============================================================================
// GroupNorm: one block per (batch, group). (verbatim from passing R6/R7)
// ============================================================================
__global__ __launch_bounds__(512) void gn_kernel(const float* __restrict__ x,
                                                 const float* __restrict__ sc,
                                                 const float* __restrict__ bi) {
    int bg = blockIdx.x;  // b*32 + g
    const float4* xp = (const float4*)(x + (size_t)bg * CPG * NTOK);
    float4* hp = (float4*)(g_h + (size_t)bg * CPG * NTOK);
    int tid = threadIdx.x;

    const int TOT4 = CPG * NTOK / 4;
    float s = 0.f, ss = 0.f;
    for (int i = tid; i < TOT4; i += 512) {
        float4 v = xp[i];
        s  += v.x + v.y + v.z + v.w;
        ss += v.x * v.x + v.y * v.y + v.z * v.z + v.w * v.w;
    }
    __shared__ float rs[16], rss[16];
    for (int o = 16; o; o >>= 1) {
        s  += __shfl_xor_sync(0xffffffffu, s, o);
        ss += __shfl_xor_sync(0xffffffffu, ss, o);
    }
    if ((tid & 31) == 0) { rs[tid >> 5] = s; rss[tid >> 5] = ss; }
    __syncthreads();
    __shared__ float mean_s, rstd_s;
    if (tid == 0) {
        float S = 0.f, SS = 0.f;
        for (int w = 0; w < 16; w++) { S += rs[w]; SS += rss[w]; }
        float inv_n = 1.0f / (float)(CPG * NTOK);
        float mean = S * inv_n;
        float var  = SS * inv_n - mean * mean;
        mean_s = mean;
        rstd_s = rsqrtf(var + 1e-6f);
    }
    __syncthreads();
    float mean = mean_s, rstd = rstd_s;
    int g = bg & (NG - 1);

    __shared__ float a_s[CPG], b_s[CPG];
    if (tid < CPG) {
        float a = rstd * sc[g * CPG + tid];
        a_s[tid] = a;
        b_s[tid] = bi[g * CPG + tid] - mean * a;
    }
    __syncthreads();
    for (int i = tid; i < TOT4; i += 512) {
        int cl = i >> 10;
        float a = a_s[cl], b2 = b_s[cl];
        float4 v = xp[i];
        v.x = v.x * a + b2; v.y = v.y * a + b2; v.z = v.z * a + b2; v.w = v.w * a + b2;
        hp[i] = v;
    }
}

// ============================================================================
// GEMM config: 128x128x16 CTA tile, 128 threads (2x2 warps), warp tile 64x64.
// Double-buffered static smem (~35KB -> 2 CTAs/SM), register prefetch,
// one sync per slab. Fragment mapping identical to verified R6/R7.
// ============================================================================
#define BM 128
#define BN 128
#define BK 16
#define LDK 136   // padded k-major row (floats)
#define LDM 20    // padded m-major row (floats)

#define DECL_MMA_STATE()                                                      \
    const int tid = threadIdx.x;                                              \
    const int wid = tid >> 5, lane = tid & 31;                                \
    const int wm = wid & 1, wn = wid >> 1;                                    \
    const int g = lane >> 2, t = lane & 3;                                    \
    float acc[4][8][4];                                                       \
    _Pragma("unroll")                                                         \
    for (int mt = 0; mt < 4; mt++)                                            \
        _Pragma("unroll")                                                     \
        for (int nt = 0; nt < 8; nt++) {                                      \
            acc[mt][nt][0] = 0.f; acc[mt][nt][1] = 0.f;                       \
            acc[mt][nt][2] = 0.f; acc[mt][nt][3] = 0.f;                       \
        }

// 32 MMAs for one 8-deep k-step; A fragments passed in
#define MMA_KSTEP(B0EXPR, B1EXPR)                                             \
    _Pragma("unroll")                                                         \
    for (int nt = 0; nt < 8; nt++) {                                          \
        const int q = wn * 64 + nt * 8 + g;                                   \
        uint32_t b0 = __float_as_uint(B0EXPR);                                \
        uint32_t b1 = __float_as_uint(B1EXPR);                                \
        _Pragma("unroll")                                                     \
        for (int mt = 0; mt < 4; mt++)                                        \
            MMA_TF32(acc[mt][nt][0], acc[mt][nt][1],                          \
                     acc[mt][nt][2], acc[mt][nt][3],                          \
                     af0[mt], af1[mt], af2[mt], af3[mt], b0, b1);             \
    }

// ============================================================================
// QKV projection: out[b,o,n] = bias[o] + sum_c W[o,c] * h[b,c,n]
// A = W (m-major), B = h (k-major). grid (32, 4, 24), 128 threads
// ============================================================================
__global__ __launch_bounds__(128) void qkv_kernel(
    const float* __restrict__ wq, const float* __restrict__ bq,
    const float* __restrict__ wk, const float* __restrict__ bk,
    const float* __restrict__ wv, const float* __restrict__ bv) {
    int z = blockIdx.z;
    int b = z / 3, wsel = z - 3 * b;
    const float* W    = (wsel == 0) ? wq : (wsel == 1) ? wk : wv;
    const float* bias = (wsel == 0) ? bq : (wsel == 1) ? bk : bv;
    float* outg       = (wsel == 0) ? g_q : (wsel == 1) ? g_k : g_v;

    const float* Hb = g_h + (size_t)b * CCH * NTOK;
    float* Ob = outg + (size_t)b * CCH * NTOK;
    int n0 = blockIdx.x * BN, m0 = blockIdx.y * BM;

    __shared__ float Asm[2][BM][LDM];
    __shared__ float Bs[2][BK][LDK];
    DECL_MMA_STATE();

    const int arow = tid >> 2, akq = (tid & 3) * 4;    // 32 rows x 4 quads
    const int brow = tid >> 5, bcol = (tid & 31) * 4;  // 4 rows x 32 quads
    const float* Ag = W + (size_t)(m0 + arow) * CCH + akq;
    const float* Bg = Hb + (size_t)brow * NTOK + n0 + bcol;

#pragma unroll
    for (int j = 0; j < 4; j++) {
        *(float4*)&Asm[0][arow + 32 * j][akq] = *(const float4*)(Ag + (size_t)(32 * j) * CCH);
        *(float4*)&Bs[0][brow + 4 * j][bcol]  = *(const float4*)(Bg + (size_t)(4 * j) * NTOK);
    }
    __syncthreads();

    const int NC = CCH / BK;
    float4 pa0, pa1, pa2, pa3, pb0, pb1, pb2, pb3;
    for (int c = 0; c < NC; c++) {
        const int s = c & 1;
        if (c + 1 < NC) {
            const float* Ap = Ag + (c + 1) * BK;
            const float* Bp = Bg + (size_t)(c + 1) * BK * NTOK;
            pa0 = *(const float4*)(Ap);
            pa1 = *(const float4*)(Ap + (size_t)32 * CCH);
            pa2 = *(const float4*)(Ap + (size_t)64 * CCH);
            pa3 = *(const float4*)(Ap + (size_t)96 * CCH);
            pb0 = *(const float4*)(Bp);
            pb1 = *(const float4*)(Bp + (size_t)4 * NTOK);
            pb2 = *(const float4*)(Bp + (size_t)8 * NTOK);
            pb3 = *(const float4*)(Bp + (size_t)12 * NTOK);
        }
#pragma unroll
        for (int kk = 0; kk < 2; kk++) {
            const int te = kk * 8 + t;
            uint32_t af0[4], af1[4], af2[4], af3[4];
#pragma unroll
            for (int mt = 0; mt < 4; mt++) {
                const int r = wm * 64 + mt * 16 + g;
                af0[mt] = __float_as_uint(Asm[s][r][te]);
                af1[mt] = __float_as_uint(Asm[s][r + 8][te]);
                af2[mt] = __float_as_uint(Asm[s][r][te + 4]);
                af3[mt] = __float_as_uint(Asm[s][r + 8][te + 4]);
            }
            MMA_KSTEP(Bs[s][te][q], Bs[s][te + 4][q]);
        }
        if (c + 1 < NC) {
            const int ns = 1 - s;
            *(float4*)&Asm[ns][arow][akq]      = pa0;
            *(float4*)&Asm[ns][arow + 32][akq] = pa1;
            *(float4*)&Asm[ns][arow + 64][akq] = pa2;
            *(float4*)&Asm[ns][arow + 96][akq] = pa3;
            *(float4*)&Bs[ns][brow][bcol]      = pb0;
            *(float4*)&Bs[ns][brow + 4][bcol]  = pb1;
            *(float4*)&Bs[ns][brow + 8][bcol]  = pb2;
            *(float4*)&Bs[ns][brow + 12][bcol] = pb3;
            __syncthreads();
        }
    }

#pragma unroll
    for (int mt = 0; mt < 4; mt++) {
        const int r0 = m0 + wm * 64 + mt * 16 + g;
        const int r1 = r0 + 8;
        const float bv0 = bias[r0], bv1 = bias[r1];
#pragma unroll
        for (int nt = 0; nt < 8; nt++) {
            const int col = n0 + wn * 64 + nt * 8 + 2 * t;
            float2 lo, hi;
            lo.x = acc[mt][nt][0] + bv0; lo.y = acc[mt][nt][1] + bv0;
            hi.x = acc[mt][nt][2] + bv1; hi.y = acc[mt][nt][3] + bv1;
            *(float2*)(Ob + (size_t)r0 * NTOK + col) = lo;
            *(float2*)(Ob + (size_t)r1 * NTOK + col) = hi;
        }
    }
}

// ============================================================================
// S = scale * Q^T K. Both operands k-major. grid (32, 32, 8), 128 threads
// ============================================================================
__global__ __launch_bounds__(128) void s_kernel() {
    int b = blockIdx.z;
    const float* Qb = g_q + (size_t)b * CCH * NTOK;
    const float* Kb = g_k + (size_t)b * CCH * NTOK;
    float* Sb = g_s + (size_t)b * NTOK * NTOK;
    int n0 = blockIdx.x * BN, m0 = blockIdx.y * BM;

    __shared__ float As[2][BK][LDK];
    __shared__ float Bs[2][BK][LDK];
    DECL_MMA_STATE();

    const int lrow = tid >> 5, lcol = (tid & 31) * 4;  // 4 rows x 32 quads
    const float* Ag = Qb + (size_t)lrow * NTOK + m0 + lcol;
    const float* Bg = Kb + (size_t)lrow * NTOK + n0 + lcol;

#pragma unroll
    for (int j = 0; j < 4; j++) {
        *(float4*)&As[0][lrow + 4 * j][lcol] = *(const float4*)(Ag + (size_t)(4 * j) * NTOK);
        *(float4*)&Bs[0][lrow + 4 * j][lcol] = *(const float4*)(Bg + (size_t)(4 * j) * NTOK);
    }
    __syncthreads();

    const int NC = CCH / BK;
    float4 pa0, pa1, pa2, pa3, pb0, pb1, pb2, pb3;
    for (int c = 0; c < NC; c++) {
        const int s = c & 1;
        if (c + 1 < NC) {
            const float* Ap = Ag + (size_t)(c + 1) * BK * NTOK;
            const float* Bp = Bg + (size_t)(c + 1) * BK * NTOK;
            pa0 = *(const float4*)(Ap);
            pa1 = *(const float4*)(Ap + (size_t)4 * NTOK);
            pa2 = *(const float4*)(Ap + (size_t)8 * NTOK);
            pa3 = *(const float4*)(Ap + (size_t)12 * NTOK);
            pb0 = *(const float4*)(Bp);
            pb1 = *(const float4*)(Bp + (size_t)4 * NTOK);
            pb2 = *(const float4*)(Bp + (size_t)8 * NTOK);
            pb3 = *(const float4*)(Bp + (size_t)12 * NTOK);
        }
#pragma unroll
        for (int kk = 0; kk < 2; kk++) {
            const int te = kk * 8 + t;
            uint32_t af0[4], af1[4], af2[4], af3[4];
#pragma unroll
            for (int mt = 0; mt < 4; mt++) {
                const int r = wm * 64 + mt * 16 + g;
                af0[mt] = __float_as_uint(As[s][te][r]);
                af1[mt] = __float_as_uint(As[s][te][r + 8]);
                af2[mt] = __float_as_uint(As[s][te + 4][r]);
                af3[mt] = __float_as_uint(As[s][te + 4][r + 8]);
            }
            MMA_KSTEP(Bs[s][te][q], Bs[s][te + 4][q]);
        }
        if (c + 1 < NC) {
            const int ns = 1 - s;
            *(float4*)&As[ns][lrow][lcol]      = pa0;
            *(float4*)&As[ns][lrow + 4][lcol]  = pa1;
            *(float4*)&As[ns][lrow + 8][lcol]  = pa2;
            *(float4*)&As[ns][lrow + 12][lcol] = pa3;
            *(float4*)&Bs[ns][lrow][lcol]      = pb0;
            *(float4*)&Bs[ns][lrow + 4][lcol]  = pb1;
            *(float4*)&Bs[ns][lrow + 8][lcol]  = pb2;
            *(float4*)&Bs[ns][lrow + 12][lcol] = pb3;
            __syncthreads();
        }
    }

    const float scale = 0.044194173824159216f;  // 512^-0.5
#pragma unroll
    for (int mt = 0; mt < 4; mt++) {
        const int r0 = m0 + wm * 64 + mt * 16 + g;
        const int r1 = r0 + 8;
#pragma unroll
        for (int nt = 0; nt < 8; nt++) {
            const int col = n0 + wn * 64 + nt * 8 + 2 * t;
            float2 lo, hi;
            lo.x = acc[mt][nt][0] * scale; lo.y = acc[mt][nt][1] * scale;
            hi.x = acc[mt][nt][2] * scale; hi.y = acc[mt][nt][3] * scale;
            *(float2*)(Sb + (size_t)r0 * NTOK + col) = lo;
            *(float2*)(Sb + (size_t)r1 * NTOK + col) = hi;
        }
    }
}

// ============================================================================
// Row softmax over g_s, in place. (verbatim from passing R6/R7)
// ============================================================================
__global__ __launch_bounds__(256) void softmax_kernel() {
    size_t row = blockIdx.x;
    float4* p = (float4*)(g_s + row * NTOK);
    int tid = threadIdx.x;

    float4 v[4];
    float m = -1e30f;
#pragma unroll
    for (int i = 0; i < 4; i++) {
        v[i] = p[tid + 256 * i];
        m = fmaxf(m, fmaxf(fmaxf(v[i].x, v[i].y), fmaxf(v[i].z, v[i].w)));
    }
    __shared__ float redm[8], reds[8];
    for (int o = 16; o; o >>= 1) m = fmaxf(m, __shfl_xor_sync(0xffffffffu, m, o));
    if ((tid & 31) == 0) redm[tid >> 5] = m;
    __syncthreads();
    float M = redm[0];
#pragma unroll
    for (int w = 1; w < 8; w++) M = fmaxf(M, redm[w]);

    float s = 0.f;
#pragma unroll
    for (int i = 0; i < 4; i++) {
        v[i].x = __expf(v[i].x - M); v[i].y = __expf(v[i].y - M);
        v[i].z = __expf(v[i].z - M); v[i].w = __expf(v[i].w - M);
        s += v[i].x + v[i].y + v[i].z + v[i].w;
    }
    for (int o = 16; o; o >>= 1) s += __shfl_xor_sync(0xffffffffu, s, o);
    if ((tid & 31) == 0) reds[tid >> 5] = s;
    __syncthreads();
    float S = 0.f;
#pragma unroll
    for (int w = 0; w < 8; w++) S += reds[w];
    float inv = 1.0f / S;
#pragma unroll
    for (int i = 0; i < 4; i++) {
        v[i].x *= inv; v[i].y *= inv; v[i].z *= inv; v[i].w *= inv;
        p[tid + 256 * i] = v[i];
    }
}

// ============================================================================
// A = V P^T, out = x + A. A = V (m-major), B = P (n-major). grid (32, 4, 8)
// ============================================================================
__global__ __launch_bounds__(128) void pv_kernel(const float* __restrict__ x,
                                                 float* __restrict__ out) {
    int b = blockIdx.z;
    const float* Vb = g_v + (size_t)b * CCH * NTOK;
    const float* Pb = g_s + (size_t)b * NTOK * NTOK;
    int n0 = blockIdx.x * BN, m0 = blockIdx.y * BM;

    __shared__ float Asm[2][BM][LDM];
    __shared__ float Bsn[2][BN][LDM];
    DECL_MMA_STATE();

    const int arow = tid >> 2, akq = (tid & 3) * 4;  // 32 rows x 4 quads
    const float* Ag = Vb + (size_t)(m0 + arow) * NTOK + akq;
    const float* Bg = Pb + (size_t)(n0 + arow) * NTOK + akq;

#pragma unroll
    for (int j = 0; j < 4; j++) {
        *(float4*)&Asm[0][arow + 32 * j][akq] = *(const float4*)(Ag + (size_t)(32 * j) * NTOK);
        *(float4*)&Bsn[0][arow + 32 * j][akq] = *(const float4*)(Bg + (size_t)(32 * j) * NTOK);
    }
    __syncthreads();

    const int NC = NTOK / BK;
    float4 pa0, pa1, pa2, pa3, pb0, pb1, pb2, pb3;
    for (int c = 0; c < NC; c++) {
        const int s = c & 1;
        if (c + 1 < NC) {
            const float* Ap = Ag + (c + 1) * BK;
            const float* Bp = Bg + (c + 1) * BK;
            pa0 = *(const float4*)(Ap);
            pa1 = *(const float4*)(Ap + (size_t)32 * NTOK);
            pa2 = *(const float4*)(Ap + (size_t)64 * NTOK);
            pa3 = *(const float4*)(Ap + (size_t)96 * NTOK);
            pb0 = *(const float4*)(Bp);
            pb1 = *(const float4*)(Bp + (size_t)32 * NTOK);
            pb2 = *(const float4*)(Bp + (size_t)64 * NTOK);
            pb3 = *(const float4*)(Bp + (size_t)96 * NTOK);
        }
#pragma unroll
        for (int kk = 0; kk < 2; kk++) {
            const int te = kk * 8 + t;
            uint32_t af0[4], af1[4], af2[4], af3[4];
#pragma unroll
            for (int mt = 0; mt < 4; mt++) {
                const int r = wm * 64 + mt * 16 + g;
                af0[mt] = __float_as_uint(Asm[s][r][te]);
                af1[mt] = __float_as_uint(Asm[s][r + 8][te]);
                af2[mt] = __float_as_uint(Asm[s][r][te + 4]);
                af3[mt] = __float_as_uint(Asm[s][r + 8][te + 4]);
            }
            MMA_KSTEP(Bsn[s][q][te], Bsn[s][q][te + 4]);
        }
        if (c + 1 < NC) {
            const int ns = 1 - s;
            *(float4*)&Asm[ns][arow][akq]      = pa0;
            *(float4*)&Asm[ns][arow + 32][akq] = pa1;
            *(float4*)&Asm[ns][arow + 64][akq] = pa2;
            *(float4*)&Asm[ns][arow + 96][akq] = pa3;
            *(float4*)&Bsn[ns][arow][akq]      = pb0;
            *(float4*)&Bsn[ns][arow + 32][akq] = pb1;
            *(float4*)&Bsn[ns][arow + 64][akq] = pb2;
            *(float4*)&Bsn[ns][arow + 96][akq] = pb3;
            __syncthreads();
        }
    }

#pragma unroll
    for (int mt = 0; mt < 4; mt++) {
        const int r0 = m0 + wm * 64 + mt * 16 + g;
        const int r1 = r0 + 8;
#pragma unroll
        for (int nt = 0; nt < 8; nt++) {
            const int col = n0 + wn * 64 + nt * 8 + 2 * t;
            size_t o0 = ((size_t)b * CCH + r0) * NTOK + col;
            size_t o1 = ((size_t)b * CCH + r1) * NTOK + col;
            float2 x0 = *(const float2*)(x + o0);
            float2 x1 = *(const float2*)(x + o1);
            float2 lo, hi;
            lo.x = acc[mt][nt][0] + x0.x; lo.y = acc[mt][nt][1] + x0.y;
            hi.x = acc[mt][nt][2] + x1.x; hi.y = acc[mt][nt][3] + x1.y;
            *(float2*)(out + o0) = lo;
            *(float2*)(out + o1) = hi;
        }
    }
}

// ============================================================================
extern "C" void kernel_launch(void* const* d_in, const int* in_sizes, int n_in,
                              void* d_out, int out_size) {
    const float* x   = (const float*)d_in[0];
    const float* gns = (const float*)d_in[1];
    const float* gnb = (const float*)d_in[2];
    const float* wq  = (const float*)d_in[3];
    const float* bq  = (const float*)d_in[4];
    const float* wk  = (const float*)d_in[5];
    const float* bk  = (const float*)d_in[6];
    const float* wv  = (const float*)d_in[7];
    const float* bv  = (const float*)d_in[8];
    float* out = (float*)d_out;
    (void)in_sizes; (void)n_in; (void)out_size;

    gn_kernel<<<BATCH * NG, 512>>>(x, gns, gnb);
    qkv_kernel<<<dim3(NTOK / BN, CCH / BM, BATCH * 3), 128>>>(wq, bq, wk, bk, wv, bv);
    s_kernel<<<dim3(NTOK / BN, NTOK / BM, BATCH), 128>>>();
    softmax_kernel<<<BATCH * NTOK, 256>>>();
    pv_kernel<<<dim3(NTOK / BN, CCH / BM, BATCH), 128>>>(x, out);
}

// round 13
// speedup vs baseline: 5.1856x; 1.5426x over previous
#include <cuda_runtime.h>
#include <cstdint>
#include <math.h>

#define CCH   512
#define NTOK  4096
#define BATCH 8
#define NG    32
#define CPG   16

#define SBN ((size_t)NTOK * CCH)    // per-batch activation stride (elements)
#define SBS ((size_t)NTOK * NTOK)   // per-batch attention stride

// -------- scratch (device globals; referenced ONLY in device code) --------
__device__ __align__(16) uint16_t g_hh[(size_t)BATCH * NTOK * CCH];  // GN out, TRANSPOSED [b][n][c]
__device__ __align__(16) uint16_t g_qt[(size_t)BATCH * NTOK * CCH];  // Qt [b][n][c]
__device__ __align__(16) uint16_t g_kt[(size_t)BATCH * NTOK * CCH];  // Kt [b][n][c]
__device__ __align__(16) uint16_t g_v [(size_t)BATCH * CCH * NTOK];  // V  [b][c][n]
__device__ __align__(16) uint16_t g_wq[CCH * CCH];
__device__ __align__(16) uint16_t g_wk[CCH * CCH];
__device__ __align__(16) uint16_t g_wv[CCH * CCH];
__device__ float g_s[(size_t)BATCH * NTOK * NTOK];                   // logits fp32 [b][i][j]
__device__ __align__(16) uint16_t g_p[(size_t)BATCH * NTOK * NTOK]; // probs fp16 [b][i][j]

// pack two fp32 -> one fp16x2 word (lo = first arg, hi = second arg)
#define PACK_H2(dst, lo, hi)                                                  \
    asm("cvt.rn.f16x2.f32 %0, %1, %2;" : "=r"(dst) : "f"(hi), "f"(lo))

#define MMA_F16(c0, c1, c2, c3, a0, a1, a2, a3, b0, b1)                       \
    asm volatile("mma.sync.aligned.m16n8k16.row.col.f32.f16.f16.f32 "         \
                 "{%0,%1,%2,%3}, {%4,%5,%6,%7}, {%8,%9}, {%0,%1,%2,%3};"      \
                 : "+f"(c0), "+f"(c1), "+f"(c2), "+f"(c3)                     \
                 : "r"(a0), "r"(a1), "r"(a2), "r"(a3), "r"(b0), "r"(b1))

// ============================================================================
// Shared GEMM machinery: CTA 128x128x32(halves), 256 threads (2x4 warps),
// warp tile 64x32. Double-buffered static smem [2][128][40] uint16, register
// prefetch (4 x uint4), one __syncthreads per slab.
// D[m][n] = sum_k A[m+m0][k] * B[n+n0][k]
// ============================================================================
#define LDHH 40   // padded smem row (halves); word stride 20 -> conflict-free frags

#define DECL_ACC()                                                            \
    const int tid = threadIdx.x;                                              \
    const int wid = tid >> 5, lane = tid & 31;                                \
    const int wm = wid & 1, wn = wid >> 1;      /* 2 (M) x 4 (N) warps */     \
    const int g = lane >> 2, t = lane & 3;                                    \
    float acc[4][4][4];                                                       \
    _Pragma("unroll")                                                         \
    for (int mt = 0; mt < 4; mt++)                                            \
        _Pragma("unroll")                                                     \
        for (int nt = 0; nt < 4; nt++) {                                      \
            acc[mt][nt][0] = 0.f; acc[mt][nt][1] = 0.f;                       \
            acc[mt][nt][2] = 0.f; acc[mt][nt][3] = 0.f;                       \
        }

#define GEMM_LOOP(LDA, LDB, KTOT)                                             \
    const int arow = tid >> 2, aq = (tid & 3) * 8;   /* 64 rows x 4 chunks */ \
    const uint16_t* Ag = Abase + (size_t)(m0 + arow) * (LDA) + aq;            \
    const uint16_t* Bg = Bbase + (size_t)(n0 + arow) * (LDB) + aq;            \
    *(uint4*)&Ash[0][arow][aq]      = *(const uint4*)(Ag);                    \
    *(uint4*)&Ash[0][arow + 64][aq] = *(const uint4*)(Ag + (size_t)64 * (LDA)); \
    *(uint4*)&Bsh[0][arow][aq]      = *(const uint4*)(Bg);                    \
    *(uint4*)&Bsh[0][arow + 64][aq] = *(const uint4*)(Bg + (size_t)64 * (LDB)); \
    __syncthreads();                                                          \
    const int NC = (KTOT) / 32;                                               \
    uint4 pa0, pa1, pb0, pb1;                                                 \
    for (int c = 0; c < NC; c++) {                                            \
        const int s = c & 1;                                                  \
        if (c + 1 < NC) {                                                     \
            const uint16_t* Ap = Ag + (size_t)(c + 1) * 32;                   \
            const uint16_t* Bp = Bg + (size_t)(c + 1) * 32;                   \
            pa0 = *(const uint4*)(Ap);                                        \
            pa1 = *(const uint4*)(Ap + (size_t)64 * (LDA));                   \
            pb0 = *(const uint4*)(Bp);                                        \
            pb1 = *(const uint4*)(Bp + (size_t)64 * (LDB));                   \
        }                                                                     \
        _Pragma("unroll")                                                     \
        for (int kk = 0; kk < 2; kk++) {                                      \
            const int ko = kk * 16 + 2 * t;                                   \
            uint32_t a0[4], a1[4], a2[4], a3[4];                              \
            _Pragma("unroll")                                                 \
            for (int mt = 0; mt < 4; mt++) {                                  \
                const int r = wm * 64 + mt * 16 + g;                          \
                a0[mt] = *(const uint32_t*)&Ash[s][r][ko];                    \
                a1[mt] = *(const uint32_t*)&Ash[s][r + 8][ko];                \
                a2[mt] = *(const uint32_t*)&Ash[s][r][ko + 8];                \
                a3[mt] = *(const uint32_t*)&Ash[s][r + 8][ko + 8];            \
            }                                                                 \
            _Pragma("unroll")                                                 \
            for (int nt = 0; nt < 4; nt++) {                                  \
                const int q = wn * 32 + nt * 8 + g;                           \
                uint32_t b0 = *(const uint32_t*)&Bsh[s][q][ko];               \
                uint32_t b1 = *(const uint32_t*)&Bsh[s][q][ko + 8];           \
                _Pragma("unroll")                                             \
                for (int mt = 0; mt < 4; mt++)                                \
                    MMA_F16(acc[mt][nt][0], acc[mt][nt][1],                   \
                            acc[mt][nt][2], acc[mt][nt][3],                   \
                            a0[mt], a1[mt], a2[mt], a3[mt], b0, b1);          \
            }                                                                 \
        }                                                                     \
        if (c + 1 < NC) {                                                     \
            const int ns = 1 - s;                                             \
            *(uint4*)&Ash[ns][arow][aq]      = pa0;                           \
            *(uint4*)&Ash[ns][arow + 64][aq] = pa1;                           \
            *(uint4*)&Bsh[ns][arow][aq]      = pb0;                           \
            *(uint4*)&Bsh[ns][arow + 64][aq] = pb1;                           \
            __syncthreads();                                                  \
        }                                                                     \
    }

// ============================================================================
// GroupNorm, transposed fp16 output: x[b,c,n] -> g_hh[b,n,c]
// ============================================================================
__global__ __launch_bounds__(512) void gn_kernel(const float* __restrict__ x,
                                                 const float* __restrict__ sc,
                                                 const float* __restrict__ bi) {
    int bg = blockIdx.x;  // b*32 + g
    int b = bg >> 5, g = bg & (NG - 1);
    const float* xg = x + (size_t)bg * CPG * NTOK;
    int tid = threadIdx.x;

    const int TOT4 = CPG * NTOK / 4;
    const float4* xp = (const float4*)xg;
    float s = 0.f, ss = 0.f;
    for (int i = tid; i < TOT4; i += 512) {
        float4 v = xp[i];
        s  += v.x + v.y + v.z + v.w;
        ss += v.x * v.x + v.y * v.y + v.z * v.z + v.w * v.w;
    }
    __shared__ float rs[16], rss[16];
    for (int o = 16; o; o >>= 1) {
        s  += __shfl_xor_sync(0xffffffffu, s, o);
        ss += __shfl_xor_sync(0xffffffffu, ss, o);
    }
    if ((tid & 31) == 0) { rs[tid >> 5] = s; rss[tid >> 5] = ss; }
    __syncthreads();
    __shared__ float mean_s, rstd_s;
    if (tid == 0) {
        float S = 0.f, SS = 0.f;
        for (int w = 0; w < 16; w++) { S += rs[w]; SS += rss[w]; }
        float inv_n = 1.0f / (float)(CPG * NTOK);
        float mean = S * inv_n;
        float var  = SS * inv_n - mean * mean;
        mean_s = mean;
        rstd_s = rsqrtf(var + 1e-6f);
    }
    __syncthreads();
    float mean = mean_s, rstd = rstd_s;

    __shared__ float a_s[CPG], b_s[CPG];
    if (tid < CPG) {
        float a = rstd * sc[g * CPG + tid];
        a_s[tid] = a;
        b_s[tid] = bi[g * CPG + tid] - mean * a;
    }
    __syncthreads();

    uint16_t* Ht = g_hh + (size_t)b * NTOK * CCH + g * CPG;
#pragma unroll
    for (int rep = 0; rep < 8; rep++) {
        int n = rep * 512 + tid;
        uint16_t* op = Ht + (size_t)n * CCH;
#pragma unroll
        for (int c = 0; c < CPG; c += 2) {
            float y0 = xg[(size_t)(c + 0) * NTOK + n] * a_s[c + 0] + b_s[c + 0];
            float y1 = xg[(size_t)(c + 1) * NTOK + n] * a_s[c + 1] + b_s[c + 1];
            uint32_t pk;
            PACK_H2(pk, y0, y1);
            *(uint32_t*)(op + c) = pk;
        }
    }
}

// ============================================================================
// Weight convert fp32 -> fp16 for all three weights. grid (256, 3).
// Destination global selected DEVICE-SIDE (never passed as an argument).
// ============================================================================
__global__ __launch_bounds__(256) void convw_kernel(const float* __restrict__ wq,
                                                    const float* __restrict__ wk,
                                                    const float* __restrict__ wv) {
    const int sel = blockIdx.y;
    const float* w = (sel == 0) ? wq : (sel == 1) ? wk : wv;
    uint16_t* o   = (sel == 0) ? g_wq : (sel == 1) ? g_wk : g_wv;
    int i = blockIdx.x * 256 + threadIdx.x;   // float4 index, 65536 total
    float4 v = *(const float4*)(w + 4 * (size_t)i);
    uint2 pk;
    PACK_H2(pk.x, v.x, v.y);
    PACK_H2(pk.y, v.z, v.w);
    *(uint2*)(o + 4 * (size_t)i) = pk;
}

// ============================================================================
// Q/K projection: Out[n][o] = H[n][:]·W[o][:] + bias[o], fp16 out.
// grid (CCH/128=4, NTOK/128=32, 16): z = b*2 + sel. Globals selected device-side.
// ============================================================================
__global__ __launch_bounds__(256) void qkproj_kernel(
    const float* __restrict__ bq, const float* __restrict__ bk) {
    __shared__ uint16_t Ash[2][128][LDHH];
    __shared__ uint16_t Bsh[2][128][LDHH];
    const int z = blockIdx.z;
    const int b = z >> 1, sel = z & 1;
    const uint16_t* Abase = g_hh + (size_t)b * SBN;
    const uint16_t* Bbase = sel ? g_wk : g_wq;
    const float* bias = sel ? bk : bq;
    uint16_t* Ob = (sel ? g_kt : g_qt) + (size_t)b * SBN;
    const int m0 = blockIdx.y * 128, n0 = blockIdx.x * 128;
    DECL_ACC();
    GEMM_LOOP(CCH, CCH, CCH);

#pragma unroll
    for (int mt = 0; mt < 4; mt++) {
        const int r0 = m0 + wm * 64 + mt * 16 + g;
        const int r1 = r0 + 8;
#pragma unroll
        for (int nt = 0; nt < 4; nt++) {
            const int col = n0 + wn * 32 + nt * 8 + 2 * t;
            float c0 = bias[col], c1 = bias[col + 1];
            uint32_t p0, p1;
            PACK_H2(p0, acc[mt][nt][0] + c0, acc[mt][nt][1] + c1);
            PACK_H2(p1, acc[mt][nt][2] + c0, acc[mt][nt][3] + c1);
            *(uint32_t*)(Ob + (size_t)r0 * CCH + col) = p0;
            *(uint32_t*)(Ob + (size_t)r1 * CCH + col) = p1;
        }
    }
}

// ============================================================================
// V projection: g_v[b][o][n] = Wv[o][:]·H[n][:] + bv[o], fp16 out.
// grid (NTOK/128=32, CCH/128=4, 8), 256 threads.
// ============================================================================
__global__ __launch_bounds__(256) void vproj_kernel(const float* __restrict__ bv) {
    __shared__ uint16_t Ash[2][128][LDHH];
    __shared__ uint16_t Bsh[2][128][LDHH];
    const int b = blockIdx.z;
    const uint16_t* Abase = g_wv;
    const uint16_t* Bbase = g_hh + (size_t)b * SBN;
    uint16_t* Ob = g_v + (size_t)b * SBN;
    const int m0 = blockIdx.y * 128, n0 = blockIdx.x * 128;
    DECL_ACC();
    GEMM_LOOP(CCH, CCH, CCH);

#pragma unroll
    for (int mt = 0; mt < 4; mt++) {
        const int r0 = m0 + wm * 64 + mt * 16 + g;
        const int r1 = r0 + 8;
        const float rb0 = bv[r0], rb1 = bv[r1];
#pragma unroll
        for (int nt = 0; nt < 4; nt++) {
            const int col = n0 + wn * 32 + nt * 8 + 2 * t;
            uint32_t p0, p1;
            PACK_H2(p0, acc[mt][nt][0] + rb0, acc[mt][nt][1] + rb0);
            PACK_H2(p1, acc[mt][nt][2] + rb1, acc[mt][nt][3] + rb1);
            *(uint32_t*)(Ob + (size_t)r0 * NTOK + col) = p0;
            *(uint32_t*)(Ob + (size_t)r1 * NTOK + col) = p1;
        }
    }
}

// ============================================================================
// S[i][j] = scale * Qt[i][:]·Kt[j][:], fp32 out. grid (32, 32, 8), 256 thr
// ============================================================================
__global__ __launch_bounds__(256) void s_kernel() {
    __shared__ uint16_t Ash[2][128][LDHH];
    __shared__ uint16_t Bsh[2][128][LDHH];
    const int b = blockIdx.z;
    const uint16_t* Abase = g_qt + (size_t)b * SBN;
    const uint16_t* Bbase = g_kt + (size_t)b * SBN;
    float* Sb = g_s + (size_t)b * SBS;
    const int m0 = blockIdx.y * 128, n0 = blockIdx.x * 128;
    DECL_ACC();
    GEMM_LOOP(CCH, CCH, CCH);

    const float scale = 0.044194173824159216f;  // 512^-0.5
#pragma unroll
    for (int mt = 0; mt < 4; mt++) {
        const int r0 = m0 + wm * 64 + mt * 16 + g;
        const int r1 = r0 + 8;
#pragma unroll
        for (int nt = 0; nt < 4; nt++) {
            const int col = n0 + wn * 32 + nt * 8 + 2 * t;
            float2 lo = { acc[mt][nt][0] * scale, acc[mt][nt][1] * scale };
            float2 hi = { acc[mt][nt][2] * scale, acc[mt][nt][3] * scale };
            *(float2*)(Sb + (size_t)r0 * NTOK + col) = lo;
            *(float2*)(Sb + (size_t)r1 * NTOK + col) = hi;
        }
    }
}

// ============================================================================
// Row softmax: read g_s fp32, write g_p fp16. One block per row.
// ============================================================================
__global__ __launch_bounds__(256) void softmax_kernel() {
    size_t row = blockIdx.x;
    const float4* p = (const float4*)(g_s + row * NTOK);
    uint16_t* ph = g_p + row * NTOK;
    int tid = threadIdx.x;

    float4 v[4];
    float m = -1e30f;
#pragma unroll
    for (int i = 0; i < 4; i++) {
        v[i] = p[tid + 256 * i];
        m = fmaxf(m, fmaxf(fmaxf(v[i].x, v[i].y), fmaxf(v[i].z, v[i].w)));
    }
    __shared__ float redm[8], reds[8];
    for (int o = 16; o; o >>= 1) m = fmaxf(m, __shfl_xor_sync(0xffffffffu, m, o));
    if ((tid & 31) == 0) redm[tid >> 5] = m;
    __syncthreads();
    float M = redm[0];
#pragma unroll
    for (int w = 1; w < 8; w++) M = fmaxf(M, redm[w]);

    float s = 0.f;
#pragma unroll
    for (int i = 0; i < 4; i++) {
        v[i].x = __expf(v[i].x - M); v[i].y = __expf(v[i].y - M);
        v[i].z = __expf(v[i].z - M); v[i].w = __expf(v[i].w - M);
        s += v[i].x + v[i].y + v[i].z + v[i].w;
    }
    for (int o = 16; o; o >>= 1) s += __shfl_xor_sync(0xffffffffu, s, o);
    if ((tid & 31) == 0) reds[tid >> 5] = s;
    __syncthreads();
    float S = 0.f;
#pragma unroll
    for (int w = 0; w < 8; w++) S += reds[w];
    float inv = 1.0f / S;
#pragma unroll
    for (int i = 0; i < 4; i++) {
        int idx = (tid + 256 * i) * 4;
        uint2 pk;
        PACK_H2(pk.x, v[i].x * inv, v[i].y * inv);
        PACK_H2(pk.y, v[i].z * inv, v[i].w * inv);
        *(uint2*)(ph + idx) = pk;
    }
}

// ============================================================================
// out[c][i] = x[c][i] + V[c][:]·P[i][:], fp32 out. grid (32, 4, 8), 256 thr
// ============================================================================
__global__ __launch_bounds__(256) void pv_kernel(const float* __restrict__ x,
                                                 float* __restrict__ out) {
    __shared__ uint16_t Ash[2][128][LDHH];
    __shared__ uint16_t Bsh[2][128][LDHH];
    const int b = blockIdx.z;
    const uint16_t* Abase = g_v + (size_t)b * SBN;
    const uint16_t* Bbase = g_p + (size_t)b * SBS;
    const size_t dbase = (size_t)b * SBN;
    const int m0 = blockIdx.y * 128, n0 = blockIdx.x * 128;
    DECL_ACC();
    GEMM_LOOP(NTOK, NTOK, NTOK);

#pragma unroll
    for (int mt = 0; mt < 4; mt++) {
        const int r0 = m0 + wm * 64 + mt * 16 + g;
        const int r1 = r0 + 8;
#pragma unroll
        for (int nt = 0; nt < 4; nt++) {
            const int col = n0 + wn * 32 + nt * 8 + 2 * t;
            size_t o0 = dbase + (size_t)r0 * NTOK + col;
            size_t o1 = dbase + (size_t)r1 * NTOK + col;
            float2 x0 = *(const float2*)(x + o0);
            float2 x1 = *(const float2*)(x + o1);
            float2 lo = { acc[mt][nt][0] + x0.x, acc[mt][nt][1] + x0.y };
            float2 hi = { acc[mt][nt][2] + x1.x, acc[mt][nt][3] + x1.y };
            *(float2*)(out + o0) = lo;
            *(float2*)(out + o1) = hi;
        }
    }
}

// ============================================================================
extern "C" void kernel_launch(void* const* d_in, const int* in_sizes, int n_in,
                              void* d_out, int out_size) {
    const float* x   = (const float*)d_in[0];
    const float* gns = (const float*)d_in[1];
    const float* gnb = (const float*)d_in[2];
    const float* wq  = (const float*)d_in[3];
    const float* bq  = (const float*)d_in[4];
    const float* wk  = (const float*)d_in[5];
    const float* bk  = (const float*)d_in[6];
    const float* wv  = (const float*)d_in[7];
    const float* bv  = (const float*)d_in[8];
    float* out = (float*)d_out;
    (void)in_sizes; (void)n_in; (void)out_size;

    gn_kernel<<<BATCH * NG, 512>>>(x, gns, gnb);
    convw_kernel<<<dim3(256, 3), 256>>>(wq, wk, wv);

    qkproj_kernel<<<dim3(CCH / 128, NTOK / 128, BATCH * 2), 256>>>(bq, bk);
    vproj_kernel<<<dim3(NTOK / 128, CCH / 128, BATCH), 256>>>(bv);
    s_kernel<<<dim3(NTOK / 128, NTOK / 128, BATCH), 256>>>();
    softmax_kernel<<<BATCH * NTOK, 256>>>();
    pv_kernel<<<dim3(NTOK / 128, CCH / 128, BATCH), 256>>>(x, out);
}

// round 14
// speedup vs baseline: 5.8509x; 1.1283x over previous
#include <cuda_runtime.h>
#include <cstdint>
#include <math.h>

#define CCH   512
#define NTOK  4096
#define BATCH 8
#define NG    32
#define CPG   16

#define SBN ((size_t)NTOK * CCH)    // per-batch activation stride (elements)
#define SBS ((size_t)NTOK * NTOK)   // per-batch attention stride

// -------- scratch (device globals; referenced ONLY in device code) --------
__device__ __align__(16) uint16_t g_hh[(size_t)BATCH * NTOK * CCH];  // GN out, TRANSPOSED [b][n][c]
__device__ __align__(16) uint16_t g_qt[(size_t)BATCH * NTOK * CCH];  // Qt [b][n][c]
__device__ __align__(16) uint16_t g_kt[(size_t)BATCH * NTOK * CCH];  // Kt [b][n][c]
__device__ __align__(16) uint16_t g_v [(size_t)BATCH * CCH * NTOK];  // V  [b][c][n]
__device__ __align__(16) uint16_t g_wq[CCH * CCH];
__device__ __align__(16) uint16_t g_wk[CCH * CCH];
__device__ __align__(16) uint16_t g_wv[CCH * CCH];
__device__ float g_s[(size_t)BATCH * NTOK * NTOK];                   // logits fp32 [b][i][j]
__device__ __align__(16) uint16_t g_p[(size_t)BATCH * NTOK * NTOK]; // probs fp16 [b][i][j]

// pack two fp32 -> one fp16x2 word (lo = first arg, hi = second arg)
#define PACK_H2(dst, lo, hi)                                                  \
    asm("cvt.rn.f16x2.f32 %0, %1, %2;" : "=r"(dst) : "f"(hi), "f"(lo))

#define MMA_F16(c0, c1, c2, c3, a0, a1, a2, a3, b0, b1)                       \
    asm volatile("mma.sync.aligned.m16n8k16.row.col.f32.f16.f16.f32 "         \
                 "{%0,%1,%2,%3}, {%4,%5,%6,%7}, {%8,%9}, {%0,%1,%2,%3};"      \
                 : "+f"(c0), "+f"(c1), "+f"(c2), "+f"(c3)                     \
                 : "r"(a0), "r"(a1), "r"(a2), "r"(a3), "r"(b0), "r"(b1))

#define LDSM_X4(r0, r1, r2, r3, addr)                                         \
    asm volatile("ldmatrix.sync.aligned.m8n8.x4.shared.b16 {%0,%1,%2,%3}, [%4];" \
                 : "=r"(r0), "=r"(r1), "=r"(r2), "=r"(r3) : "r"(addr))

__device__ __forceinline__ uint32_t smem_u32(const void* p) {
    uint32_t a;
    asm("{ .reg .u64 t; cvta.to.shared.u64 t, %1; cvt.u32.u64 %0, t; }" : "=r"(a) : "l"(p));
    return a;
}

// ============================================================================
// Shared GEMM machinery: CTA 128x128x32(halves), 256 threads (2x4 warps),
// warp tile 64x32. Double-buffered static smem [2][128][40] uint16, register
// prefetch (4 x uint4), one __syncthreads per slab. Fragments via ldmatrix.x4.
// D[m][n] = sum_k A[m+m0][k] * B[n+n0][k]
// ============================================================================
#define LDHH 40                       // padded smem row (halves)
#define STAGEB (128 * LDHH * 2)       // stage size in bytes = 10240

#define DECL_ACC()                                                            \
    const int tid = threadIdx.x;                                              \
    const int wid = tid >> 5, lane = tid & 31;                                \
    const int wm = wid & 1, wn = wid >> 1;      /* 2 (M) x 4 (N) warps */     \
    const int g = lane >> 2, t = lane & 3;                                    \
    float acc[4][4][4];                                                       \
    _Pragma("unroll")                                                         \
    for (int mt = 0; mt < 4; mt++)                                            \
        _Pragma("unroll")                                                     \
        for (int nt = 0; nt < 4; nt++) {                                      \
            acc[mt][nt][0] = 0.f; acc[mt][nt][1] = 0.f;                       \
            acc[mt][nt][2] = 0.f; acc[mt][nt][3] = 0.f;                       \
        }

// ldmatrix lane->row/col mapping:
//   A x4 groups: (row+0,k0) (row+8,k0) (row+0,k8) (row+8,k8)  -> a0,a1,a2,a3
//   B x4 groups: (nt0,k0) (nt0,k8) (nt0+1,k0) (nt0+1,k8)      -> b0,b1,b0',b1'
#define GEMM_LOOP(LDA, LDB, KTOT)                                             \
    const int arow = tid >> 2, aq = (tid & 3) * 8;   /* 64 rows x 4 chunks */ \
    const uint16_t* Ag = Abase + (size_t)(m0 + arow) * (LDA) + aq;            \
    const uint16_t* Bg = Bbase + (size_t)(n0 + arow) * (LDB) + aq;            \
    *(uint4*)&Ash[0][arow][aq]      = *(const uint4*)(Ag);                    \
    *(uint4*)&Ash[0][arow + 64][aq] = *(const uint4*)(Ag + (size_t)64 * (LDA)); \
    *(uint4*)&Bsh[0][arow][aq]      = *(const uint4*)(Bg);                    \
    *(uint4*)&Bsh[0][arow + 64][aq] = *(const uint4*)(Bg + (size_t)64 * (LDB)); \
    const uint32_t aB32 = smem_u32(&Ash[0][0][0]) +                           \
        (uint32_t)((((lane & 7) + ((lane >> 3) & 1) * 8 + wm * 64) * LDHH +   \
                    (lane >> 4) * 8) * 2);                                    \
    const uint32_t bB32 = smem_u32(&Bsh[0][0][0]) +                           \
        (uint32_t)((((lane & 7) + (lane >> 4) * 8 + wn * 32) * LDHH +         \
                    ((lane >> 3) & 1) * 8) * 2);                              \
    __syncthreads();                                                          \
    const int NC = (KTOT) / 32;                                               \
    uint4 pa0, pa1, pb0, pb1;                                                 \
    for (int c = 0; c < NC; c++) {                                            \
        const int s = c & 1;                                                  \
        if (c + 1 < NC) {                                                     \
            const uint16_t* Ap = Ag + (size_t)(c + 1) * 32;                   \
            const uint16_t* Bp = Bg + (size_t)(c + 1) * 32;                   \
            pa0 = *(const uint4*)(Ap);                                        \
            pa1 = *(const uint4*)(Ap + (size_t)64 * (LDA));                   \
            pb0 = *(const uint4*)(Bp);                                        \
            pb1 = *(const uint4*)(Bp + (size_t)64 * (LDB));                   \
        }                                                                     \
        const uint32_t sOff = (uint32_t)s * STAGEB;                           \
        _Pragma("unroll")                                                     \
        for (int kk = 0; kk < 2; kk++) {                                      \
            uint32_t a0[4], a1[4], a2[4], a3[4];                              \
            _Pragma("unroll")                                                 \
            for (int mt = 0; mt < 4; mt++)                                    \
                LDSM_X4(a0[mt], a1[mt], a2[mt], a3[mt],                       \
                        aB32 + sOff + (uint32_t)((mt * 16 * LDHH + kk * 16) * 2)); \
            uint32_t b0[4], b1[4];                                            \
            LDSM_X4(b0[0], b1[0], b0[1], b1[1],                               \
                    bB32 + sOff + (uint32_t)((kk * 16) * 2));                 \
            LDSM_X4(b0[2], b1[2], b0[3], b1[3],                               \
                    bB32 + sOff + (uint32_t)((16 * LDHH + kk * 16) * 2));     \
            _Pragma("unroll")                                                 \
            for (int nt = 0; nt < 4; nt++)                                    \
                _Pragma("unroll")                                             \
                for (int mt = 0; mt < 4; mt++)                                \
                    MMA_F16(acc[mt][nt][0], acc[mt][nt][1],                   \
                            acc[mt][nt][2], acc[mt][nt][3],                   \
                            a0[mt], a1[mt], a2[mt], a3[mt], b0[nt], b1[nt]);  \
        }                                                                     \
        if (c + 1 < NC) {                                                     \
            const int ns = 1 - s;                                             \
            *(uint4*)&Ash[ns][arow][aq]      = pa0;                           \
            *(uint4*)&Ash[ns][arow + 64][aq] = pa1;                           \
            *(uint4*)&Bsh[ns][arow][aq]      = pb0;                           \
            *(uint4*)&Bsh[ns][arow + 64][aq] = pb1;                           \
            __syncthreads();                                                  \
        }                                                                     \
    }

// ============================================================================
// GroupNorm, transposed fp16 output: x[b,c,n] -> g_hh[b,n,c]
// ============================================================================
__global__ __launch_bounds__(512) void gn_kernel(const float* __restrict__ x,
                                                 const float* __restrict__ sc,
                                                 const float* __restrict__ bi) {
    int bg = blockIdx.x;  // b*32 + g
    int b = bg >> 5, g = bg & (NG - 1);
    const float* xg = x + (size_t)bg * CPG * NTOK;
    int tid = threadIdx.x;

    const int TOT4 = CPG * NTOK / 4;
    const float4* xp = (const float4*)xg;
    float s = 0.f, ss = 0.f;
    for (int i = tid; i < TOT4; i += 512) {
        float4 v = xp[i];
        s  += v.x + v.y + v.z + v.w;
        ss += v.x * v.x + v.y * v.y + v.z * v.z + v.w * v.w;
    }
    __shared__ float rs[16], rss[16];
    for (int o = 16; o; o >>= 1) {
        s  += __shfl_xor_sync(0xffffffffu, s, o);
        ss += __shfl_xor_sync(0xffffffffu, ss, o);
    }
    if ((tid & 31) == 0) { rs[tid >> 5] = s; rss[tid >> 5] = ss; }
    __syncthreads();
    __shared__ float mean_s, rstd_s;
    if (tid == 0) {
        float S = 0.f, SS = 0.f;
        for (int w = 0; w < 16; w++) { S += rs[w]; SS += rss[w]; }
        float inv_n = 1.0f / (float)(CPG * NTOK);
        float mean = S * inv_n;
        float var  = SS * inv_n - mean * mean;
        mean_s = mean;
        rstd_s = rsqrtf(var + 1e-6f);
    }
    __syncthreads();
    float mean = mean_s, rstd = rstd_s;

    __shared__ float a_s[CPG], b_s[CPG];
    if (tid < CPG) {
        float a = rstd * sc[g * CPG + tid];
        a_s[tid] = a;
        b_s[tid] = bi[g * CPG + tid] - mean * a;
    }
    __syncthreads();

    uint16_t* Ht = g_hh + (size_t)b * NTOK * CCH + g * CPG;
#pragma unroll
    for (int rep = 0; rep < 8; rep++) {
        int n = rep * 512 + tid;
        uint16_t* op = Ht + (size_t)n * CCH;
#pragma unroll
        for (int c = 0; c < CPG; c += 2) {
            float y0 = xg[(size_t)(c + 0) * NTOK + n] * a_s[c + 0] + b_s[c + 0];
            float y1 = xg[(size_t)(c + 1) * NTOK + n] * a_s[c + 1] + b_s[c + 1];
            uint32_t pk;
            PACK_H2(pk, y0, y1);
            *(uint32_t*)(op + c) = pk;
        }
    }
}

// ============================================================================
// Weight convert fp32 -> fp16 for all three weights. grid (256, 3).
// ============================================================================
__global__ __launch_bounds__(256) void convw_kernel(const float* __restrict__ wq,
                                                    const float* __restrict__ wk,
                                                    const float* __restrict__ wv) {
    const int sel = blockIdx.y;
    const float* w = (sel == 0) ? wq : (sel == 1) ? wk : wv;
    uint16_t* o   = (sel == 0) ? g_wq : (sel == 1) ? g_wk : g_wv;
    int i = blockIdx.x * 256 + threadIdx.x;   // float4 index, 65536 total
    float4 v = *(const float4*)(w + 4 * (size_t)i);
    uint2 pk;
    PACK_H2(pk.x, v.x, v.y);
    PACK_H2(pk.y, v.z, v.w);
    *(uint2*)(o + 4 * (size_t)i) = pk;
}

// ============================================================================
// Q/K projection: Out[n][o] = H[n][:]·W[o][:] + bias[o], fp16 out.
// grid (CCH/128=4, NTOK/128=32, 16): z = b*2 + sel.
// ============================================================================
__global__ __launch_bounds__(256) void qkproj_kernel(
    const float* __restrict__ bq, const float* __restrict__ bk) {
    __shared__ uint16_t Ash[2][128][LDHH];
    __shared__ uint16_t Bsh[2][128][LDHH];
    const int z = blockIdx.z;
    const int b = z >> 1, sel = z & 1;
    const uint16_t* Abase = g_hh + (size_t)b * SBN;
    const uint16_t* Bbase = sel ? g_wk : g_wq;
    const float* bias = sel ? bk : bq;
    uint16_t* Ob = (sel ? g_kt : g_qt) + (size_t)b * SBN;
    const int m0 = blockIdx.y * 128, n0 = blockIdx.x * 128;
    DECL_ACC();
    GEMM_LOOP(CCH, CCH, CCH);

#pragma unroll
    for (int mt = 0; mt < 4; mt++) {
        const int r0 = m0 + wm * 64 + mt * 16 + g;
        const int r1 = r0 + 8;
#pragma unroll
        for (int nt = 0; nt < 4; nt++) {
            const int col = n0 + wn * 32 + nt * 8 + 2 * t;
            float c0 = bias[col], c1 = bias[col + 1];
            uint32_t p0, p1;
            PACK_H2(p0, acc[mt][nt][0] + c0, acc[mt][nt][1] + c1);
            PACK_H2(p1, acc[mt][nt][2] + c0, acc[mt][nt][3] + c1);
            *(uint32_t*)(Ob + (size_t)r0 * CCH + col) = p0;
            *(uint32_t*)(Ob + (size_t)r1 * CCH + col) = p1;
        }
    }
}

// ============================================================================
// V projection: g_v[b][o][n] = Wv[o][:]·H[n][:] + bv[o], fp16 out.
// grid (NTOK/128=32, CCH/128=4, 8)
// ============================================================================
__global__ __launch_bounds__(256) void vproj_kernel(const float* __restrict__ bv) {
    __shared__ uint16_t Ash[2][128][LDHH];
    __shared__ uint16_t Bsh[2][128][LDHH];
    const int b = blockIdx.z;
    const uint16_t* Abase = g_wv;
    const uint16_t* Bbase = g_hh + (size_t)b * SBN;
    uint16_t* Ob = g_v + (size_t)b * SBN;
    const int m0 = blockIdx.y * 128, n0 = blockIdx.x * 128;
    DECL_ACC();
    GEMM_LOOP(CCH, CCH, CCH);

#pragma unroll
    for (int mt = 0; mt < 4; mt++) {
        const int r0 = m0 + wm * 64 + mt * 16 + g;
        const int r1 = r0 + 8;
        const float rb0 = bv[r0], rb1 = bv[r1];
#pragma unroll
        for (int nt = 0; nt < 4; nt++) {
            const int col = n0 + wn * 32 + nt * 8 + 2 * t;
            uint32_t p0, p1;
            PACK_H2(p0, acc[mt][nt][0] + rb0, acc[mt][nt][1] + rb0);
            PACK_H2(p1, acc[mt][nt][2] + rb1, acc[mt][nt][3] + rb1);
            *(uint32_t*)(Ob + (size_t)r0 * NTOK + col) = p0;
            *(uint32_t*)(Ob + (size_t)r1 * NTOK + col) = p1;
        }
    }
}

// ============================================================================
// S[i][j] = scale * Qt[i][:]·Kt[j][:], fp32 out. grid (32, 32, 8)
// ============================================================================
__global__ __launch_bounds__(256) void s_kernel() {
    __shared__ uint16_t Ash[2][128][LDHH];
    __shared__ uint16_t Bsh[2][128][LDHH];
    const int b = blockIdx.z;
    const uint16_t* Abase = g_qt + (size_t)b * SBN;
    const uint16_t* Bbase = g_kt + (size_t)b * SBN;
    float* Sb = g_s + (size_t)b * SBS;
    const int m0 = blockIdx.y * 128, n0 = blockIdx.x * 128;
    DECL_ACC();
    GEMM_LOOP(CCH, CCH, CCH);

    const float scale = 0.044194173824159216f;  // 512^-0.5
#pragma unroll
    for (int mt = 0; mt < 4; mt++) {
        const int r0 = m0 + wm * 64 + mt * 16 + g;
        const int r1 = r0 + 8;
#pragma unroll
        for (int nt = 0; nt < 4; nt++) {
            const int col = n0 + wn * 32 + nt * 8 + 2 * t;
            float2 lo = { acc[mt][nt][0] * scale, acc[mt][nt][1] * scale };
            float2 hi = { acc[mt][nt][2] * scale, acc[mt][nt][3] * scale };
            *(float2*)(Sb + (size_t)r0 * NTOK + col) = lo;
            *(float2*)(Sb + (size_t)r1 * NTOK + col) = hi;
        }
    }
}

// ============================================================================
// Row softmax: read g_s fp32, write g_p fp16. One block per row.
// ============================================================================
__global__ __launch_bounds__(256) void softmax_kernel() {
    size_t row = blockIdx.x;
    const float4* p = (const float4*)(g_s + row * NTOK);
    uint16_t* ph = g_p + row * NTOK;
    int tid = threadIdx.x;

    float4 v[4];
    float m = -1e30f;
#pragma unroll
    for (int i = 0; i < 4; i++) {
        v[i] = p[tid + 256 * i];
        m = fmaxf(m, fmaxf(fmaxf(v[i].x, v[i].y), fmaxf(v[i].z, v[i].w)));
    }
    __shared__ float redm[8], reds[8];
    for (int o = 16; o; o >>= 1) m = fmaxf(m, __shfl_xor_sync(0xffffffffu, m, o));
    if ((tid & 31) == 0) redm[tid >> 5] = m;
    __syncthreads();
    float M = redm[0];
#pragma unroll
    for (int w = 1; w < 8; w++) M = fmaxf(M, redm[w]);

    float s = 0.f;
#pragma unroll
    for (int i = 0; i < 4; i++) {
        v[i].x = __expf(v[i].x - M); v[i].y = __expf(v[i].y - M);
        v[i].z = __expf(v[i].z - M); v[i].w = __expf(v[i].w - M);
        s += v[i].x + v[i].y + v[i].z + v[i].w;
    }
    for (int o = 16; o; o >>= 1) s += __shfl_xor_sync(0xffffffffu, s, o);
    if ((tid & 31) == 0) reds[tid >> 5] = s;
    __syncthreads();
    float S = 0.f;
#pragma unroll
    for (int w = 0; w < 8; w++) S += reds[w];
    float inv = 1.0f / S;
#pragma unroll
    for (int i = 0; i < 4; i++) {
        int idx = (tid + 256 * i) * 4;
        uint2 pk;
        PACK_H2(pk.x, v[i].x * inv, v[i].y * inv);
        PACK_H2(pk.y, v[i].z * inv, v[i].w * inv);
        *(uint2*)(ph + idx) = pk;
    }
}

// ============================================================================
// out[c][i] = x[c][i] + V[c][:]·P[i][:], fp32 out. grid (32, 4, 8)
// ============================================================================
__global__ __launch_bounds__(256) void pv_kernel(const float* __restrict__ x,
                                                 float* __restrict__ out) {
    __shared__ uint16_t Ash[2][128][LDHH];
    __shared__ uint16_t Bsh[2][128][LDHH];
    const int b = blockIdx.z;
    const uint16_t* Abase = g_v + (size_t)b * SBN;
    const uint16_t* Bbase = g_p + (size_t)b * SBS;
    const size_t dbase = (size_t)b * SBN;
    const int m0 = blockIdx.y * 128, n0 = blockIdx.x * 128;
    DECL_ACC();
    GEMM_LOOP(NTOK, NTOK, NTOK);

#pragma unroll
    for (int mt = 0; mt < 4; mt++) {
        const int r0 = m0 + wm * 64 + mt * 16 + g;
        const int r1 = r0 + 8;
#pragma unroll
        for (int nt = 0; nt < 4; nt++) {
            const int col = n0 + wn * 32 + nt * 8 + 2 * t;
            size_t o0 = dbase + (size_t)r0 * NTOK + col;
            size_t o1 = dbase + (size_t)r1 * NTOK + col;
            float2 x0 = *(const float2*)(x + o0);
            float2 x1 = *(const float2*)(x + o1);
            float2 lo = { acc[mt][nt][0] + x0.x, acc[mt][nt][1] + x0.y };
            float2 hi = { acc[mt][nt][2] + x1.x, acc[mt][nt][3] + x1.y };
            *(float2*)(out + o0) = lo;
            *(float2*)(out + o1) = hi;
        }
    }
}

// ============================================================================
extern "C" void kernel_launch(void* const* d_in, const int* in_sizes, int n_in,
                              void* d_out, int out_size) {
    const float* x   = (const float*)d_in[0];
    const float* gns = (const float*)d_in[1];
    const float* gnb = (const float*)d_in[2];
    const float* wq  = (const float*)d_in[3];
    const float* bq  = (const float*)d_in[4];
    const float* wk  = (const float*)d_in[5];
    const float* bk  = (const float*)d_in[6];
    const float* wv  = (const float*)d_in[7];
    const float* bv  = (const float*)d_in[8];
    float* out = (float*)d_out;
    (void)in_sizes; (void)n_in; (void)out_size;

    gn_kernel<<<BATCH * NG, 512>>>(x, gns, gnb);
    convw_kernel<<<dim3(256, 3), 256>>>(wq, wk, wv);

    qkproj_kernel<<<dim3(CCH / 128, NTOK / 128, BATCH * 2), 256>>>(bq, bk);
    vproj_kernel<<<dim3(NTOK / 128, CCH / 128, BATCH), 256>>>(bv);
    s_kernel<<<dim3(NTOK / 128, NTOK / 128, BATCH), 256>>>();
    softmax_kernel<<<BATCH * NTOK, 256>>>();
    pv_kernel<<<dim3(NTOK / 128, CCH / 128, BATCH), 256>>>(x, out);
}